// round 6
// baseline (speedup 1.0000x reference)
#include <cuda_runtime.h>
#include <cuda_bf16.h>
#include <cuda_fp16.h>
#include <cstdint>
#include <math.h>

// Problem constants
constexpr int DM = 1024;   // d_model
constexpr int H  = 16;     // heads
constexpr int DH = 64;     // head dim
constexpr int B  = 4;      // batch
constexpr int S  = 2048;   // seq len
constexpr int M  = B * S;  // 8192 rows

// Scratch (allocation-free rule: __device__ globals)
__device__ __half g_xhi[(size_t)M * DM];
__device__ __half g_xlo[(size_t)M * DM];
__device__ __half g_whi[(size_t)4 * DM * DM];          // weights: fp16 RN only
__device__ __nv_bfloat16 g_qkvhi[(size_t)3 * M * DM];  // q,k,v head-major bf16
__device__ __nv_bfloat16 g_qkvlo[(size_t)3 * M * DM];
__device__ __half g_aohi[(size_t)M * DM];
__device__ __half g_aolo[(size_t)M * DM];

// ---------------------------------------------------------------------------
// PTX helpers (compute_103-safe)
// ---------------------------------------------------------------------------
__device__ __forceinline__ uint32_t smem_u32(const void* p) {
    uint32_t a;
    asm("{ .reg .u64 t; cvta.to.shared.u64 t, %1; cvt.u32.u64 %0, t; }"
        : "=r"(a) : "l"(p));
    return a;
}
__device__ __forceinline__ void cp16(uint32_t saddr, const void* gaddr) {
    asm volatile("cp.async.cg.shared.global [%0], [%1], 16;"
                 :: "r"(saddr), "l"(gaddr) : "memory");
}
__device__ __forceinline__ void cp_commit() {
    asm volatile("cp.async.commit_group;" ::: "memory");
}
template <int N>
__device__ __forceinline__ void cp_waitg() {
    asm volatile("cp.async.wait_group %0;" :: "n"(N) : "memory");
}
__device__ __forceinline__ void ldsm4(uint32_t* r, uint32_t addr) {
    asm volatile("ldmatrix.sync.aligned.m8n8.x4.shared.b16 {%0,%1,%2,%3}, [%4];"
                 : "=r"(r[0]), "=r"(r[1]), "=r"(r[2]), "=r"(r[3]) : "r"(addr));
}
__device__ __forceinline__ void ldsm4t(uint32_t* r, uint32_t addr) {
    asm volatile("ldmatrix.sync.aligned.m8n8.x4.trans.shared.b16 {%0,%1,%2,%3}, [%4];"
                 : "=r"(r[0]), "=r"(r[1]), "=r"(r[2]), "=r"(r[3]) : "r"(addr));
}
// bf16 mma (attention)
__device__ __forceinline__ void mma16816(float* c, const uint32_t* a, const uint32_t* b) {
    asm volatile(
        "mma.sync.aligned.m16n8k16.row.col.f32.bf16.bf16.f32 "
        "{%0,%1,%2,%3}, {%4,%5,%6,%7}, {%8,%9}, {%0,%1,%2,%3};"
        : "+f"(c[0]), "+f"(c[1]), "+f"(c[2]), "+f"(c[3])
        : "r"(a[0]), "r"(a[1]), "r"(a[2]), "r"(a[3]), "r"(b[0]), "r"(b[1]));
}
// fp16 mma (projection GEMMs)
__device__ __forceinline__ void mma16816h(float* c, const uint32_t* a, const uint32_t* b) {
    asm volatile(
        "mma.sync.aligned.m16n8k16.row.col.f32.f16.f16.f32 "
        "{%0,%1,%2,%3}, {%4,%5,%6,%7}, {%8,%9}, {%0,%1,%2,%3};"
        : "+f"(c[0]), "+f"(c[1]), "+f"(c[2]), "+f"(c[3])
        : "r"(a[0]), "r"(a[1]), "r"(a[2]), "r"(a[3]), "r"(b[0]), "r"(b[1]));
}
// bf16 packers (truncation hi / RN residual lo)
__device__ __forceinline__ uint32_t pk_hi2(float a, float b) {
    return __byte_perm(__float_as_uint(a), __float_as_uint(b), 0x7632);
}
__device__ __forceinline__ uint32_t pk_lo2(float a, float b) {
    float la = a - __uint_as_float(__float_as_uint(a) & 0xFFFF0000u);
    float lb = b - __uint_as_float(__float_as_uint(b) & 0xFFFF0000u);
    uint32_t r;
    asm("cvt.rn.bf16x2.f32 %0, %1, %2;" : "=r"(r) : "f"(lb), "f"(la));
    return r;
}
// fp16 RN pack (a -> low half)
__device__ __forceinline__ uint32_t pkh2(float a, float b) {
    uint32_t r;
    asm("cvt.rn.f16x2.f32 %0, %1, %2;" : "=r"(r) : "f"(b), "f"(a));
    return r;
}
// fp16 hi/lo split of a float pair
__device__ __forceinline__ void split_f16(float a, float b, uint32_t& hi, uint32_t& lo) {
    __half ha = __float2half_rn(a);
    __half hb = __float2half_rn(b);
    hi = ((uint32_t)__half_as_ushort(hb) << 16) | __half_as_ushort(ha);
    lo = pkh2(a - __half2float(ha), b - __half2float(hb));
}

// ---------------------------------------------------------------------------
// Merged split: x -> fp16 hi/lo, 4 weights -> fp16 RN. One launch.
// ---------------------------------------------------------------------------
constexpr int XN4 = (M * DM) / 4;     // 2M float4
constexpr int WN4 = (DM * DM) / 4;    // 256K float4
constexpr int SPLIT_TOTAL = XN4 + 4 * WN4;

__global__ __launch_bounds__(256) void split_all(
    const float4* __restrict__ x,
    const float4* __restrict__ w0, const float4* __restrict__ w1,
    const float4* __restrict__ w2, const float4* __restrict__ w3,
    uint32_t* __restrict__ xhi, uint32_t* __restrict__ xlo,
    uint32_t* __restrict__ whi) {
    int i = blockIdx.x * 256 + threadIdx.x;
    if (i >= SPLIT_TOTAL) return;
    if (i < XN4) {
        float4 v = x[i];
        uint32_t h0, l0, h1, l1;
        split_f16(v.x, v.y, h0, l0);
        split_f16(v.z, v.w, h1, l1);
        xhi[2 * i] = h0; xhi[2 * i + 1] = h1;
        xlo[2 * i] = l0; xlo[2 * i + 1] = l1;
    } else {
        int j = i - XN4;
        int widx = j >> 18;            // / WN4
        int wj = j & (WN4 - 1);
        const float4* ws[4] = {w0, w1, w2, w3};
        float4 v = ws[widx][wj];
        size_t o = (size_t)widx * (2 * WN4) + 2 * wj;
        whi[o]     = pkh2(v.x, v.y);
        whi[o + 1] = pkh2(v.z, v.w);
    }
}

// ---------------------------------------------------------------------------
// fp16 2-term GEMM: C[M,N] = (Ah+Al)[M,K] @ Wh[N,K]^T, fp32 accumulate.
// BM=128 BN=128 BK=32, 256 thr (8 warps 2x4), warp tile 64x32, 3-stage
// cp.async. OUTBF=1: fused QKV (grid.x=24, widx=bn>>3), bf16 hi/lo head-major.
// ---------------------------------------------------------------------------
constexpr int ROWB = 80;
constexpr int TILEB = 128 * ROWB;            // 10240
constexpr int A_REG = 3 * 2 * TILEB;         // 3 stages x {hi,lo}
constexpr int GEMM_SMEM = A_REG + 3 * TILEB; // + B hi (3 stages) = 92160
constexpr int NKT = DM / 32;

template <int OUTBF>
__global__ __launch_bounds__(256) void gemm_f16(const __half* __restrict__ Ah,
                                                const __half* __restrict__ Al,
                                                const __half* __restrict__ Wh,
                                                float* __restrict__ C,
                                                __nv_bfloat16* __restrict__ QKVhi,
                                                __nv_bfloat16* __restrict__ QKVlo) {
    extern __shared__ char smem[];
    const uint32_t sb = smem_u32(smem);
    const int tid = threadIdx.x;
    const int lane = tid & 31;
    const int wid = tid >> 5;
    const int warpM = wid & 1;
    const int warpN = wid >> 1;
    const int bn = blockIdx.x;
    const int bm = blockIdx.y;
    const int widx = (OUTBF == 1) ? (bn >> 3) : 0;
    const int bnl = (OUTBF == 1) ? (bn & 7) : bn;
    const int rowA0 = bm * 128;
    const int rowB0 = bnl * 128;
    const __half* Bh = Wh + (size_t)widx * DM * DM;

    const int lr0 = tid >> 2;
    const int lc = (tid & 3) * 8;

    auto load_stage = [&](int kt, int buf) {
        const size_t gkoff = (size_t)kt * 32 + lc;
#pragma unroll
        for (int it = 0; it < 2; it++) {
            int r = lr0 + it * 64;
            uint32_t so = (uint32_t)(r * ROWB + (tid & 3) * 16);
            size_t ga = (size_t)(rowA0 + r) * DM + gkoff;
            size_t gb = (size_t)(rowB0 + r) * DM + gkoff;
            uint32_t abase = sb + buf * 2 * TILEB;
            uint32_t bbase = sb + A_REG + buf * TILEB;
            cp16(abase + so,         Ah + ga);
            cp16(abase + TILEB + so, Al + ga);
            cp16(bbase + so,         Bh + gb);
        }
        cp_commit();
    };

    float acc[4][4][4];
#pragma unroll
    for (int i = 0; i < 4; i++)
#pragma unroll
        for (int j = 0; j < 4; j++)
#pragma unroll
            for (int e = 0; e < 4; e++) acc[i][j][e] = 0.f;

    load_stage(0, 0);
    load_stage(1, 1);

    const int a_r = (lane & 15);
    const int a_c8 = (lane >> 4) * 8;
    const int b_r = ((lane >> 4) * 8) + (lane & 7);
    const int b_c8 = ((lane >> 3) & 1) * 8;

    for (int kt = 0; kt < NKT; kt++) {
        const int buf = kt % 3;
        cp_waitg<1>();
        __syncthreads();

        int ktn = kt + 2;
        if (ktn > NKT - 1) ktn = NKT - 1;
        load_stage(ktn, (kt + 2) % 3);

        const uint32_t aHi = sb + buf * 2 * TILEB;
        const uint32_t aLo = aHi + TILEB;
        const uint32_t bHi = sb + A_REG + buf * TILEB;
        const int mrow = warpM * 64 + a_r;
        const int nrow = warpN * 32 + b_r;

#pragma unroll
        for (int ks = 0; ks < 2; ks++) {
            uint32_t ah[4][4], al[4][4], bh[2][4];
            const uint32_t acol = (uint32_t)((ks * 16 + a_c8) * 2);
            const uint32_t bcol = (uint32_t)((ks * 16 + b_c8) * 2);
#pragma unroll
            for (int mt = 0; mt < 4; mt++) {
                uint32_t ro = (uint32_t)((mrow + mt * 16) * ROWB) + acol;
                ldsm4(ah[mt], aHi + ro);
                ldsm4(al[mt], aLo + ro);
            }
#pragma unroll
            for (int np = 0; np < 2; np++) {
                uint32_t ro = (uint32_t)((nrow + np * 16) * ROWB) + bcol;
                ldsm4(bh[np], bHi + ro);
            }
#pragma unroll
            for (int mt = 0; mt < 4; mt++)
#pragma unroll
                for (int np = 0; np < 2; np++)
#pragma unroll
                    for (int ns = 0; ns < 2; ns++) {
                        float* c = acc[mt][np * 2 + ns];
                        mma16816h(c, ah[mt], &bh[np][ns * 2]);
                        mma16816h(c, al[mt], &bh[np][ns * 2]);
                    }
        }
        __syncthreads();
    }

    const int rbase = bm * 128 + warpM * 64 + (lane >> 2);
    const int cbase = bnl * 128 + warpN * 32 + (lane & 3) * 2;
    __nv_bfloat16* Chi = QKVhi + (size_t)widx * M * DM;
    __nv_bfloat16* Clo = QKVlo + (size_t)widx * M * DM;
#pragma unroll
    for (int mt = 0; mt < 4; mt++) {
#pragma unroll
        for (int nt = 0; nt < 4; nt++) {
            int row = rbase + mt * 16;
            int col = cbase + nt * 8;
#pragma unroll
            for (int half = 0; half < 2; half++) {
                int r = row + half * 8;
                float vx = acc[mt][nt][half * 2];
                float vy = acc[mt][nt][half * 2 + 1];
                if (OUTBF == 0) {
                    *(float2*)(C + (size_t)r * DM + col) = make_float2(vx, vy);
                } else {
                    int b_ = r >> 11;
                    int s_ = r & 2047;
                    int h_ = col >> 6;
                    int d_ = col & 63;
                    size_t idx = ((((size_t)b_ * H + h_) * S + s_) << 6) + d_;
                    *(uint32_t*)(Chi + idx) = pk_hi2(vx, vy);
                    *(uint32_t*)(Clo + idx) = pk_lo2(vx, vy);
                }
            }
        }
    }
}

// ---------------------------------------------------------------------------
// Tensor-core causal flash attention, bf16 3-term split.
// 256 thr (8 warps), 128 queries/CTA (16 per warp), KV tiles of 64,
// double-buffered cp.async. Writes AO as fp16 hi/lo [b, s, h*64+d].
// ---------------------------------------------------------------------------
constexpr int AROWB = 144;
constexpr int ATILE = 64 * AROWB;       // 9216
constexpr int ASTG = 4 * ATILE;         // Kh, Kl, Vh, Vl
constexpr int ATT_SMEM = 2 * ASTG;      // 73728

__global__ __launch_bounds__(256) void attn_mma(
    const __nv_bfloat16* __restrict__ QKVh, const __nv_bfloat16* __restrict__ QKVl,
    __half* __restrict__ AOh, __half* __restrict__ AOl) {
    extern __shared__ char smem[];
    const uint32_t sb = smem_u32(smem);
    const int tid = threadIdx.x;
    const int lane = tid & 31;
    const int wid = tid >> 5;           // 0..7
    const int qt = blockIdx.x;          // 0..15 (128 queries each)
    const int h = blockIdx.y;
    const int b = blockIdx.z;
    const size_t hb = (((size_t)b * H + h) * S) * DH;
    const __nv_bfloat16* Qh = QKVh;
    const __nv_bfloat16* Ql = QKVl;
    const __nv_bfloat16* Kh = QKVh + (size_t)M * DM;
    const __nv_bfloat16* Kl = QKVl + (size_t)M * DM;
    const __nv_bfloat16* Vh = QKVh + (size_t)2 * M * DM;
    const __nv_bfloat16* Vl = QKVl + (size_t)2 * M * DM;

    // Stage Q (128x64 hi at buf0[0..2ATILE), lo at buf0[2ATILE..4ATILE))
#pragma unroll
    for (int i = 0; i < 4; i++) {
        int id = tid + i * 256;         // 0..1023
        int r = id >> 3, c = id & 7;    // r: 0..127
        uint32_t so = (uint32_t)(r * AROWB + c * 16);
        size_t g = hb + (size_t)(qt * 128 + r) * DH + c * 8;
        cp16(sb + so, Qh + g);
        cp16(sb + 2 * ATILE + so, Ql + g);
    }
    cp_commit();
    cp_waitg<0>();
    __syncthreads();

    uint32_t qh[4][4], ql[4][4];
    {
        int row = wid * 16 + (lane & 15);   // 0..127
#pragma unroll
        for (int ks = 0; ks < 4; ks++) {
            uint32_t off = (uint32_t)(row * AROWB + (ks * 16 + (lane >> 4) * 8) * 2);
            ldsm4(qh[ks], sb + off);
            ldsm4(ql[ks], sb + 2 * ATILE + off);
        }
    }
    __syncthreads();

    float ov[8][4];
#pragma unroll
    for (int o = 0; o < 8; o++)
#pragma unroll
        for (int e = 0; e < 4; e++) ov[o][e] = 0.f;
    float m0 = -1e30f, m1 = -1e30f, l0 = 0.f, l1 = 0.f;

    const int nkt = 2 * qt + 2;

    auto load_kv = [&](int kt, int bufi) {
        uint32_t base = sb + bufi * ASTG;
#pragma unroll
        for (int i = 0; i < 2; i++) {
            int id = tid + i * 256;     // 0..511
            int r = id >> 3, c = id & 7;
            uint32_t so = (uint32_t)(r * AROWB + c * 16);
            size_t g = hb + (size_t)(kt * 64 + r) * DH + c * 8;
            cp16(base + so,             Kh + g);
            cp16(base + ATILE + so,     Kl + g);
            cp16(base + 2 * ATILE + so, Vh + g);
            cp16(base + 3 * ATILE + so, Vl + g);
        }
        cp_commit();
    };
    load_kv(0, 0);

    // per-thread query rows
    const int q0 = qt * 128 + wid * 16 + (lane >> 2);
    const int q1 = q0 + 8;

    for (int kt = 0; kt < nkt; kt++) {
        const int buf = kt & 1;
        if (kt + 1 < nkt) { load_kv(kt + 1, buf ^ 1); cp_waitg<1>(); }
        else              { cp_waitg<0>(); }
        __syncthreads();
        const uint32_t kb = sb + buf * ASTG;

        // S = Qh*Kh + Ql*Kh + Qh*Kl
        float sf[8][4];
#pragma unroll
        for (int o = 0; o < 8; o++)
#pragma unroll
            for (int e = 0; e < 4; e++) sf[o][e] = 0.f;

#pragma unroll
        for (int ks = 0; ks < 4; ks++) {
#pragma unroll
            for (int np = 0; np < 4; np++) {
                uint32_t kh4[4], kl4[4];
                uint32_t ro = (uint32_t)(
                    (np * 16 + (lane >> 4) * 8 + (lane & 7)) * AROWB +
                    (ks * 16 + ((lane >> 3) & 1) * 8) * 2);
                ldsm4(kh4, kb + ro);
                ldsm4(kl4, kb + ATILE + ro);
#pragma unroll
                for (int ns = 0; ns < 2; ns++) {
                    float* c = sf[np * 2 + ns];
                    mma16816(c, qh[ks], &kh4[ns * 2]);
                    mma16816(c, qh[ks], &kl4[ns * 2]);
                    mma16816(c, ql[ks], &kh4[ns * 2]);
                }
            }
        }

        // online softmax (fp32); mask only on the last two tiles
        const bool diag = (kt >= 2 * qt);
        const int kt64 = kt * 64;
        float mx0 = -1e30f, mx1 = -1e30f;
#pragma unroll
        for (int o = 0; o < 8; o++) {
#pragma unroll
            for (int e = 0; e < 2; e++) {
                int keyg = kt64 + o * 8 + (lane & 3) * 2 + e;
                float v0 = sf[o][e] * 0.125f;
                float v1 = sf[o][2 + e] * 0.125f;
                if (diag && keyg > q0) v0 = -1e30f;
                if (diag && keyg > q1) v1 = -1e30f;
                sf[o][e] = v0;
                sf[o][2 + e] = v1;
                mx0 = fmaxf(mx0, v0);
                mx1 = fmaxf(mx1, v1);
            }
        }
        mx0 = fmaxf(mx0, __shfl_xor_sync(0xffffffffu, mx0, 1));
        mx0 = fmaxf(mx0, __shfl_xor_sync(0xffffffffu, mx0, 2));
        mx1 = fmaxf(mx1, __shfl_xor_sync(0xffffffffu, mx1, 1));
        mx1 = fmaxf(mx1, __shfl_xor_sync(0xffffffffu, mx1, 2));
        const float mn0 = fmaxf(m0, mx0);
        const float mn1 = fmaxf(m1, mx1);
        const float es0 = __expf(m0 - mn0);
        const float es1 = __expf(m1 - mn1);
        m0 = mn0; m1 = mn1;

        float rs0 = 0.f, rs1 = 0.f;
#pragma unroll
        for (int o = 0; o < 8; o++) {
#pragma unroll
            for (int e = 0; e < 2; e++) {
                float p0 = __expf(sf[o][e] - mn0);
                float p1 = __expf(sf[o][2 + e] - mn1);
                sf[o][e] = p0;
                sf[o][2 + e] = p1;
                rs0 += p0;
                rs1 += p1;
            }
        }
        rs0 += __shfl_xor_sync(0xffffffffu, rs0, 1);
        rs0 += __shfl_xor_sync(0xffffffffu, rs0, 2);
        rs1 += __shfl_xor_sync(0xffffffffu, rs1, 1);
        rs1 += __shfl_xor_sync(0xffffffffu, rs1, 2);
        l0 = l0 * es0 + rs0;
        l1 = l1 * es1 + rs1;
#pragma unroll
        for (int o = 0; o < 8; o++) {
            ov[o][0] *= es0; ov[o][1] *= es0;
            ov[o][2] *= es1; ov[o][3] *= es1;
        }

        // O += Ph*Vh + Pl*Vh + Ph*Vl
#pragma unroll
        for (int kp = 0; kp < 4; kp++) {
            uint32_t pah[4], pal[4];
            pah[0] = pk_hi2(sf[2 * kp][0], sf[2 * kp][1]);
            pah[1] = pk_hi2(sf[2 * kp][2], sf[2 * kp][3]);
            pah[2] = pk_hi2(sf[2 * kp + 1][0], sf[2 * kp + 1][1]);
            pah[3] = pk_hi2(sf[2 * kp + 1][2], sf[2 * kp + 1][3]);
            pal[0] = pk_lo2(sf[2 * kp][0], sf[2 * kp][1]);
            pal[1] = pk_lo2(sf[2 * kp][2], sf[2 * kp][3]);
            pal[2] = pk_lo2(sf[2 * kp + 1][0], sf[2 * kp + 1][1]);
            pal[3] = pk_lo2(sf[2 * kp + 1][2], sf[2 * kp + 1][3]);
#pragma unroll
            for (int dp = 0; dp < 4; dp++) {
                uint32_t bvh[4], bvl[4];
                uint32_t vo = (uint32_t)(
                    (kp * 16 + (lane & 15)) * AROWB +
                    (dp * 16 + (lane >> 4) * 8) * 2);
                ldsm4t(bvh, kb + 2 * ATILE + vo);
                ldsm4t(bvl, kb + 3 * ATILE + vo);
#pragma unroll
                for (int ns = 0; ns < 2; ns++) {
                    float* o_ = ov[dp * 2 + ns];
                    mma16816(o_, pah, &bvh[ns * 2]);
                    mma16816(o_, pal, &bvh[ns * 2]);
                    mma16816(o_, pah, &bvl[ns * 2]);
                }
            }
        }
        __syncthreads();
    }

    // epilogue: normalize, split to fp16 hi/lo, write [b, s, h*64 + d]
    const float inv0 = 1.f / l0;
    const float inv1 = 1.f / l1;
    const int s0 = qt * 128 + wid * 16 + (lane >> 2);
    const size_t row0 = ((size_t)b * S + s0) * DM + h * DH;
    const size_t row1 = row0 + (size_t)8 * DM;
#pragma unroll
    for (int o = 0; o < 8; o++) {
        int d = o * 8 + (lane & 3) * 2;
        uint32_t hi0, lo0, hi1, lo1;
        split_f16(ov[o][0] * inv0, ov[o][1] * inv0, hi0, lo0);
        split_f16(ov[o][2] * inv1, ov[o][3] * inv1, hi1, lo1);
        *(uint32_t*)(AOh + row0 + d) = hi0;
        *(uint32_t*)(AOl + row0 + d) = lo0;
        *(uint32_t*)(AOh + row1 + d) = hi1;
        *(uint32_t*)(AOl + row1 + d) = lo1;
    }
}

// ---------------------------------------------------------------------------
extern "C" void kernel_launch(void* const* d_in, const int* in_sizes, int n_in,
                              void* d_out, int out_size) {
    const float* w[4] = {nullptr, nullptr, nullptr, nullptr};
    const float* x = nullptr;
    int wn = 0;
    for (int i = 0; i < n_in; i++) {
        if (in_sizes[i] == DM * DM && wn < 4) {
            w[wn++] = (const float*)d_in[i];
        } else if (in_sizes[i] == B * S * DM) {
            x = (const float*)d_in[i];
        }
    }

    __half *xhi, *xlo, *whi, *aohi, *aolo;
    __nv_bfloat16 *qkvhi, *qkvlo;
    cudaGetSymbolAddress((void**)&xhi, g_xhi);
    cudaGetSymbolAddress((void**)&xlo, g_xlo);
    cudaGetSymbolAddress((void**)&whi, g_whi);
    cudaGetSymbolAddress((void**)&qkvhi, g_qkvhi);
    cudaGetSymbolAddress((void**)&qkvlo, g_qkvlo);
    cudaGetSymbolAddress((void**)&aohi, g_aohi);
    cudaGetSymbolAddress((void**)&aolo, g_aolo);

    cudaFuncSetAttribute(gemm_f16<0>, cudaFuncAttributeMaxDynamicSharedMemorySize, GEMM_SMEM);
    cudaFuncSetAttribute(gemm_f16<1>, cudaFuncAttributeMaxDynamicSharedMemorySize, GEMM_SMEM);
    cudaFuncSetAttribute(attn_mma, cudaFuncAttributeMaxDynamicSharedMemorySize, ATT_SMEM);

    // One merged split launch
    split_all<<<(SPLIT_TOTAL + 255) / 256, 256>>>(
        (const float4*)x, (const float4*)w[0], (const float4*)w[1],
        (const float4*)w[2], (const float4*)w[3],
        (uint32_t*)xhi, (uint32_t*)xlo, (uint32_t*)whi);

    // Fused QKV projection
    dim3 qkvgrid(3 * DM / 128, M / 128);  // (24, 64)
    gemm_f16<1><<<qkvgrid, 256, GEMM_SMEM>>>(xhi, xlo, whi, nullptr, qkvhi, qkvlo);

    dim3 agrid(S / 128, H, B);  // (16, 16, 4)
    attn_mma<<<agrid, 256, ATT_SMEM>>>(qkvhi, qkvlo, aohi, aolo);

    dim3 ogrid(DM / 128, M / 128);  // (8, 64)
    gemm_f16<0><<<ogrid, 256, GEMM_SMEM>>>(aohi, aolo, whi + (size_t)3 * DM * DM,
                                           (float*)d_out, nullptr, nullptr);
}

// round 7
// speedup vs baseline: 1.0505x; 1.0505x over previous
#include <cuda_runtime.h>
#include <cuda_bf16.h>
#include <cuda_fp16.h>
#include <cstdint>
#include <math.h>

// Problem constants
constexpr int DM = 1024;   // d_model
constexpr int H  = 16;     // heads
constexpr int DH = 64;     // head dim
constexpr int B  = 4;      // batch
constexpr int S  = 2048;   // seq len
constexpr int M  = B * S;  // 8192 rows

// Scratch (allocation-free rule: __device__ globals)
__device__ __half g_xhi[(size_t)M * DM];
__device__ __half g_xlo[(size_t)M * DM];
__device__ __half g_whi[(size_t)4 * DM * DM];          // weights: fp16 RN only
__device__ __nv_bfloat16 g_qkvhi[(size_t)3 * M * DM];  // q,k,v head-major bf16
__device__ __nv_bfloat16 g_qkvlo[(size_t)3 * M * DM];
__device__ __half g_aohi[(size_t)M * DM];
__device__ __half g_aolo[(size_t)M * DM];

// ---------------------------------------------------------------------------
// PTX helpers (compute_103-safe)
// ---------------------------------------------------------------------------
__device__ __forceinline__ uint32_t smem_u32(const void* p) {
    uint32_t a;
    asm("{ .reg .u64 t; cvta.to.shared.u64 t, %1; cvt.u32.u64 %0, t; }"
        : "=r"(a) : "l"(p));
    return a;
}
__device__ __forceinline__ void cp16(uint32_t saddr, const void* gaddr) {
    asm volatile("cp.async.cg.shared.global [%0], [%1], 16;"
                 :: "r"(saddr), "l"(gaddr) : "memory");
}
__device__ __forceinline__ void cp_commit() {
    asm volatile("cp.async.commit_group;" ::: "memory");
}
template <int N>
__device__ __forceinline__ void cp_waitg() {
    asm volatile("cp.async.wait_group %0;" :: "n"(N) : "memory");
}
__device__ __forceinline__ void ldsm4(uint32_t* r, uint32_t addr) {
    asm volatile("ldmatrix.sync.aligned.m8n8.x4.shared.b16 {%0,%1,%2,%3}, [%4];"
                 : "=r"(r[0]), "=r"(r[1]), "=r"(r[2]), "=r"(r[3]) : "r"(addr));
}
__device__ __forceinline__ void ldsm4t(uint32_t* r, uint32_t addr) {
    asm volatile("ldmatrix.sync.aligned.m8n8.x4.trans.shared.b16 {%0,%1,%2,%3}, [%4];"
                 : "=r"(r[0]), "=r"(r[1]), "=r"(r[2]), "=r"(r[3]) : "r"(addr));
}
// bf16 mma (attention)
__device__ __forceinline__ void mma16816(float* c, const uint32_t* a, const uint32_t* b) {
    asm volatile(
        "mma.sync.aligned.m16n8k16.row.col.f32.bf16.bf16.f32 "
        "{%0,%1,%2,%3}, {%4,%5,%6,%7}, {%8,%9}, {%0,%1,%2,%3};"
        : "+f"(c[0]), "+f"(c[1]), "+f"(c[2]), "+f"(c[3])
        : "r"(a[0]), "r"(a[1]), "r"(a[2]), "r"(a[3]), "r"(b[0]), "r"(b[1]));
}
// fp16 mma (projection GEMMs)
__device__ __forceinline__ void mma16816h(float* c, const uint32_t* a, const uint32_t* b) {
    asm volatile(
        "mma.sync.aligned.m16n8k16.row.col.f32.f16.f16.f32 "
        "{%0,%1,%2,%3}, {%4,%5,%6,%7}, {%8,%9}, {%0,%1,%2,%3};"
        : "+f"(c[0]), "+f"(c[1]), "+f"(c[2]), "+f"(c[3])
        : "r"(a[0]), "r"(a[1]), "r"(a[2]), "r"(a[3]), "r"(b[0]), "r"(b[1]));
}
// bf16 packers (truncation hi / RN residual lo)
__device__ __forceinline__ uint32_t pk_hi2(float a, float b) {
    return __byte_perm(__float_as_uint(a), __float_as_uint(b), 0x7632);
}
__device__ __forceinline__ uint32_t pk_lo2(float a, float b) {
    float la = a - __uint_as_float(__float_as_uint(a) & 0xFFFF0000u);
    float lb = b - __uint_as_float(__float_as_uint(b) & 0xFFFF0000u);
    uint32_t r;
    asm("cvt.rn.bf16x2.f32 %0, %1, %2;" : "=r"(r) : "f"(lb), "f"(la));
    return r;
}
// fp16 RN pack (a -> low half)
__device__ __forceinline__ uint32_t pkh2(float a, float b) {
    uint32_t r;
    asm("cvt.rn.f16x2.f32 %0, %1, %2;" : "=r"(r) : "f"(b), "f"(a));
    return r;
}
// fp16 hi/lo split of a float pair
__device__ __forceinline__ void split_f16(float a, float b, uint32_t& hi, uint32_t& lo) {
    __half ha = __float2half_rn(a);
    __half hb = __float2half_rn(b);
    hi = ((uint32_t)__half_as_ushort(hb) << 16) | __half_as_ushort(ha);
    lo = pkh2(a - __half2float(ha), b - __half2float(hb));
}

// ---------------------------------------------------------------------------
// Merged split: x -> fp16 hi/lo, 4 weights -> fp16 RN. One launch.
// ---------------------------------------------------------------------------
constexpr int XN4 = (M * DM) / 4;     // 2M float4
constexpr int WN4 = (DM * DM) / 4;    // 256K float4
constexpr int SPLIT_TOTAL = XN4 + 4 * WN4;

__global__ __launch_bounds__(256) void split_all(
    const float4* __restrict__ x,
    const float4* __restrict__ w0, const float4* __restrict__ w1,
    const float4* __restrict__ w2, const float4* __restrict__ w3,
    uint32_t* __restrict__ xhi, uint32_t* __restrict__ xlo,
    uint32_t* __restrict__ whi) {
    int i = blockIdx.x * 256 + threadIdx.x;
    if (i >= SPLIT_TOTAL) return;
    if (i < XN4) {
        float4 v = x[i];
        uint32_t h0, l0, h1, l1;
        split_f16(v.x, v.y, h0, l0);
        split_f16(v.z, v.w, h1, l1);
        xhi[2 * i] = h0; xhi[2 * i + 1] = h1;
        xlo[2 * i] = l0; xlo[2 * i + 1] = l1;
    } else {
        int j = i - XN4;
        int widx = j >> 18;            // / WN4
        int wj = j & (WN4 - 1);
        const float4* ws[4] = {w0, w1, w2, w3};
        float4 v = ws[widx][wj];
        size_t o = (size_t)widx * (2 * WN4) + 2 * wj;
        whi[o]     = pkh2(v.x, v.y);
        whi[o + 1] = pkh2(v.z, v.w);
    }
}

// ---------------------------------------------------------------------------
// fp16 2-term GEMM: C[M,N] = (Ah+Al)[M,K] @ Wh[N,K]^T, fp32 accumulate.
// BM=128 BN=128 BK=32, 256 thr (8 warps 2x4), warp tile 64x32, 3-stage
// cp.async pipeline, ONE barrier per k-iteration.
// OUTBF=1: fused QKV (grid.x=24, widx=bn>>3), bf16 hi/lo head-major.
// ---------------------------------------------------------------------------
constexpr int ROWB = 80;
constexpr int TILEB = 128 * ROWB;            // 10240
constexpr int A_REG = 3 * 2 * TILEB;         // 3 stages x {hi,lo}
constexpr int GEMM_SMEM = A_REG + 3 * TILEB; // + B hi (3 stages) = 92160
constexpr int NKT = DM / 32;

template <int OUTBF>
__global__ __launch_bounds__(256) void gemm_f16(const __half* __restrict__ Ah,
                                                const __half* __restrict__ Al,
                                                const __half* __restrict__ Wh,
                                                float* __restrict__ C,
                                                __nv_bfloat16* __restrict__ QKVhi,
                                                __nv_bfloat16* __restrict__ QKVlo) {
    extern __shared__ char smem[];
    const uint32_t sb = smem_u32(smem);
    const int tid = threadIdx.x;
    const int lane = tid & 31;
    const int wid = tid >> 5;
    const int warpM = wid & 1;
    const int warpN = wid >> 1;
    const int bn = blockIdx.x;
    const int bm = blockIdx.y;
    const int widx = (OUTBF == 1) ? (bn >> 3) : 0;
    const int bnl = (OUTBF == 1) ? (bn & 7) : bn;
    const int rowA0 = bm * 128;
    const int rowB0 = bnl * 128;
    const __half* Bh = Wh + (size_t)widx * DM * DM;

    const int lr0 = tid >> 2;
    const int lc = (tid & 3) * 8;

    auto load_stage = [&](int kt, int buf) {
        const size_t gkoff = (size_t)kt * 32 + lc;
#pragma unroll
        for (int it = 0; it < 2; it++) {
            int r = lr0 + it * 64;
            uint32_t so = (uint32_t)(r * ROWB + (tid & 3) * 16);
            size_t ga = (size_t)(rowA0 + r) * DM + gkoff;
            size_t gb = (size_t)(rowB0 + r) * DM + gkoff;
            uint32_t abase = sb + buf * 2 * TILEB;
            uint32_t bbase = sb + A_REG + buf * TILEB;
            cp16(abase + so,         Ah + ga);
            cp16(abase + TILEB + so, Al + ga);
            cp16(bbase + so,         Bh + gb);
        }
        cp_commit();
    };

    float acc[4][4][4];
#pragma unroll
    for (int i = 0; i < 4; i++)
#pragma unroll
        for (int j = 0; j < 4; j++)
#pragma unroll
            for (int e = 0; e < 4; e++) acc[i][j][e] = 0.f;

    load_stage(0, 0);
    load_stage(1, 1);

    const int a_r = (lane & 15);
    const int a_c8 = (lane >> 4) * 8;
    const int b_r = ((lane >> 4) * 8) + (lane & 7);
    const int b_c8 = ((lane >> 3) & 1) * 8;

    for (int kt = 0; kt < NKT; kt++) {
        const int buf = kt % 3;
        cp_waitg<1>();
        __syncthreads();   // single barrier: data(kt) visible AND compute(kt-1) done

        // prefetch stage kt+2 — overwrites buf (kt-1)%3, safe after the barrier
        int ktn = kt + 2;
        if (ktn > NKT - 1) ktn = NKT - 1;
        load_stage(ktn, (kt + 2) % 3);

        const uint32_t aHi = sb + buf * 2 * TILEB;
        const uint32_t aLo = aHi + TILEB;
        const uint32_t bHi = sb + A_REG + buf * TILEB;
        const int mrow = warpM * 64 + a_r;
        const int nrow = warpN * 32 + b_r;

#pragma unroll
        for (int ks = 0; ks < 2; ks++) {
            uint32_t ah[4][4], al[4][4], bh[2][4];
            const uint32_t acol = (uint32_t)((ks * 16 + a_c8) * 2);
            const uint32_t bcol = (uint32_t)((ks * 16 + b_c8) * 2);
#pragma unroll
            for (int mt = 0; mt < 4; mt++) {
                uint32_t ro = (uint32_t)((mrow + mt * 16) * ROWB) + acol;
                ldsm4(ah[mt], aHi + ro);
                ldsm4(al[mt], aLo + ro);
            }
#pragma unroll
            for (int np = 0; np < 2; np++) {
                uint32_t ro = (uint32_t)((nrow + np * 16) * ROWB) + bcol;
                ldsm4(bh[np], bHi + ro);
            }
#pragma unroll
            for (int mt = 0; mt < 4; mt++)
#pragma unroll
                for (int np = 0; np < 2; np++)
#pragma unroll
                    for (int ns = 0; ns < 2; ns++) {
                        float* c = acc[mt][np * 2 + ns];
                        mma16816h(c, ah[mt], &bh[np][ns * 2]);
                        mma16816h(c, al[mt], &bh[np][ns * 2]);
                    }
        }
    }

    const int rbase = bm * 128 + warpM * 64 + (lane >> 2);
    const int cbase = bnl * 128 + warpN * 32 + (lane & 3) * 2;
    __nv_bfloat16* Chi = QKVhi + (size_t)widx * M * DM;
    __nv_bfloat16* Clo = QKVlo + (size_t)widx * M * DM;
#pragma unroll
    for (int mt = 0; mt < 4; mt++) {
#pragma unroll
        for (int nt = 0; nt < 4; nt++) {
            int row = rbase + mt * 16;
            int col = cbase + nt * 8;
#pragma unroll
            for (int half = 0; half < 2; half++) {
                int r = row + half * 8;
                float vx = acc[mt][nt][half * 2];
                float vy = acc[mt][nt][half * 2 + 1];
                if (OUTBF == 0) {
                    *(float2*)(C + (size_t)r * DM + col) = make_float2(vx, vy);
                } else {
                    int b_ = r >> 11;
                    int s_ = r & 2047;
                    int h_ = col >> 6;
                    int d_ = col & 63;
                    size_t idx = ((((size_t)b_ * H + h_) * S + s_) << 6) + d_;
                    *(uint32_t*)(Chi + idx) = pk_hi2(vx, vy);
                    *(uint32_t*)(Clo + idx) = pk_lo2(vx, vy);
                }
            }
        }
    }
}

// ---------------------------------------------------------------------------
// Tensor-core causal flash attention, bf16 3-term split (R5 shape: 128 thr,
// 64 queries/CTA). One barrier per KV tile; exp2-domain softmax.
// Writes AO as fp16 hi/lo [b, s, h*64+d].
// ---------------------------------------------------------------------------
constexpr int AROWB = 144;
constexpr int ATILE = 64 * AROWB;
constexpr int ASTG = 4 * ATILE;
constexpr int ATT_SMEM = 2 * ASTG;
constexpr float SC2 = 0.125f * 1.4426950408889634f;  // (1/sqrt(64)) * log2(e)

__global__ __launch_bounds__(128) void attn_mma(
    const __nv_bfloat16* __restrict__ QKVh, const __nv_bfloat16* __restrict__ QKVl,
    __half* __restrict__ AOh, __half* __restrict__ AOl) {
    extern __shared__ char smem[];
    const uint32_t sb = smem_u32(smem);
    const int tid = threadIdx.x;
    const int lane = tid & 31;
    const int wid = tid >> 5;
    const int qt = blockIdx.x;
    const int h = blockIdx.y;
    const int b = blockIdx.z;
    const size_t hb = (((size_t)b * H + h) * S) * DH;
    const __nv_bfloat16* Qh = QKVh;
    const __nv_bfloat16* Ql = QKVl;
    const __nv_bfloat16* Kh = QKVh + (size_t)M * DM;
    const __nv_bfloat16* Kl = QKVl + (size_t)M * DM;
    const __nv_bfloat16* Vh = QKVh + (size_t)2 * M * DM;
    const __nv_bfloat16* Vl = QKVl + (size_t)2 * M * DM;

    // Stage Q (64x64 hi/lo) into buffer 0, extract to regs
#pragma unroll
    for (int i = 0; i < 4; i++) {
        int id = tid + i * 128;
        int r = id >> 3, c = id & 7;
        uint32_t so = (uint32_t)(r * AROWB + c * 16);
        size_t g = hb + (size_t)(qt * 64 + r) * DH + c * 8;
        cp16(sb + so, Qh + g);
        cp16(sb + ATILE + so, Ql + g);
    }
    cp_commit();
    cp_waitg<0>();
    __syncthreads();

    uint32_t qh[4][4], ql[4][4];
    {
        int row = wid * 16 + (lane & 15);
#pragma unroll
        for (int ks = 0; ks < 4; ks++) {
            uint32_t off = (uint32_t)(row * AROWB + (ks * 16 + (lane >> 4) * 8) * 2);
            ldsm4(qh[ks], sb + off);
            ldsm4(ql[ks], sb + ATILE + off);
        }
    }
    __syncthreads();

    float ov[8][4];
#pragma unroll
    for (int o = 0; o < 8; o++)
#pragma unroll
        for (int e = 0; e < 4; e++) ov[o][e] = 0.f;
    float m0 = -1e30f, m1 = -1e30f, l0 = 0.f, l1 = 0.f;

    const int nkt = qt + 1;

    auto load_kv = [&](int kt, int bufi) {
        uint32_t base = sb + bufi * ASTG;
#pragma unroll
        for (int i = 0; i < 4; i++) {
            int id = tid + i * 128;
            int r = id >> 3, c = id & 7;
            uint32_t so = (uint32_t)(r * AROWB + c * 16);
            size_t g = hb + (size_t)(kt * 64 + r) * DH + c * 8;
            cp16(base + so,             Kh + g);
            cp16(base + ATILE + so,     Kl + g);
            cp16(base + 2 * ATILE + so, Vh + g);
            cp16(base + 3 * ATILE + so, Vl + g);
        }
        cp_commit();
    };
    load_kv(0, 0);

    const int q0 = qt * 64 + wid * 16 + (lane >> 2);
    const int q1 = q0 + 8;

    for (int kt = 0; kt < nkt; kt++) {
        const int buf = kt & 1;
        cp_waitg<0>();
        __syncthreads();   // single barrier: tile(kt) visible AND compute(kt-1) done

        // prefetch next tile into buf^1 (read at kt-1; safe after barrier)
        if (kt + 1 < nkt) load_kv(kt + 1, buf ^ 1);

        const uint32_t kb = sb + buf * ASTG;

        // S = Qh*Kh + Ql*Kh + Qh*Kl
        float sf[8][4];
#pragma unroll
        for (int o = 0; o < 8; o++)
#pragma unroll
            for (int e = 0; e < 4; e++) sf[o][e] = 0.f;

#pragma unroll
        for (int ks = 0; ks < 4; ks++) {
#pragma unroll
            for (int np = 0; np < 4; np++) {
                uint32_t kh4[4], kl4[4];
                uint32_t ro = (uint32_t)(
                    (np * 16 + (lane >> 4) * 8 + (lane & 7)) * AROWB +
                    (ks * 16 + ((lane >> 3) & 1) * 8) * 2);
                ldsm4(kh4, kb + ro);
                ldsm4(kl4, kb + ATILE + ro);
#pragma unroll
                for (int ns = 0; ns < 2; ns++) {
                    float* c = sf[np * 2 + ns];
                    mma16816(c, qh[ks], &kh4[ns * 2]);
                    mma16816(c, qh[ks], &kl4[ns * 2]);
                    mma16816(c, ql[ks], &kh4[ns * 2]);
                }
            }
        }

        // online softmax in exp2 domain
        const bool diag = (kt == qt);
        float mx0 = -1e30f, mx1 = -1e30f;
#pragma unroll
        for (int o = 0; o < 8; o++) {
#pragma unroll
            for (int e = 0; e < 2; e++) {
                int keyl = o * 8 + (lane & 3) * 2 + e;
                float v0 = sf[o][e] * SC2;
                float v1 = sf[o][2 + e] * SC2;
                if (diag && keyl > q0 - qt * 64) v0 = -1e30f;
                if (diag && keyl > q1 - qt * 64) v1 = -1e30f;
                sf[o][e] = v0;
                sf[o][2 + e] = v1;
                mx0 = fmaxf(mx0, v0);
                mx1 = fmaxf(mx1, v1);
            }
        }
        mx0 = fmaxf(mx0, __shfl_xor_sync(0xffffffffu, mx0, 1));
        mx0 = fmaxf(mx0, __shfl_xor_sync(0xffffffffu, mx0, 2));
        mx1 = fmaxf(mx1, __shfl_xor_sync(0xffffffffu, mx1, 1));
        mx1 = fmaxf(mx1, __shfl_xor_sync(0xffffffffu, mx1, 2));
        const float mn0 = fmaxf(m0, mx0);
        const float mn1 = fmaxf(m1, mx1);
        const float es0 = exp2f(m0 - mn0);
        const float es1 = exp2f(m1 - mn1);
        m0 = mn0; m1 = mn1;

        float rs0 = 0.f, rs1 = 0.f;
#pragma unroll
        for (int o = 0; o < 8; o++) {
#pragma unroll
            for (int e = 0; e < 2; e++) {
                float p0 = exp2f(sf[o][e] - mn0);
                float p1 = exp2f(sf[o][2 + e] - mn1);
                sf[o][e] = p0;
                sf[o][2 + e] = p1;
                rs0 += p0;
                rs1 += p1;
            }
        }
        rs0 += __shfl_xor_sync(0xffffffffu, rs0, 1);
        rs0 += __shfl_xor_sync(0xffffffffu, rs0, 2);
        rs1 += __shfl_xor_sync(0xffffffffu, rs1, 1);
        rs1 += __shfl_xor_sync(0xffffffffu, rs1, 2);
        l0 = l0 * es0 + rs0;
        l1 = l1 * es1 + rs1;
#pragma unroll
        for (int o = 0; o < 8; o++) {
            ov[o][0] *= es0; ov[o][1] *= es0;
            ov[o][2] *= es1; ov[o][3] *= es1;
        }

        // O += Ph*Vh + Pl*Vh + Ph*Vl
#pragma unroll
        for (int kp = 0; kp < 4; kp++) {
            uint32_t pah[4], pal[4];
            pah[0] = pk_hi2(sf[2 * kp][0], sf[2 * kp][1]);
            pah[1] = pk_hi2(sf[2 * kp][2], sf[2 * kp][3]);
            pah[2] = pk_hi2(sf[2 * kp + 1][0], sf[2 * kp + 1][1]);
            pah[3] = pk_hi2(sf[2 * kp + 1][2], sf[2 * kp + 1][3]);
            pal[0] = pk_lo2(sf[2 * kp][0], sf[2 * kp][1]);
            pal[1] = pk_lo2(sf[2 * kp][2], sf[2 * kp][3]);
            pal[2] = pk_lo2(sf[2 * kp + 1][0], sf[2 * kp + 1][1]);
            pal[3] = pk_lo2(sf[2 * kp + 1][2], sf[2 * kp + 1][3]);
#pragma unroll
            for (int dp = 0; dp < 4; dp++) {
                uint32_t bvh[4], bvl[4];
                uint32_t vo = (uint32_t)(
                    (kp * 16 + (lane & 15)) * AROWB +
                    (dp * 16 + (lane >> 4) * 8) * 2);
                ldsm4t(bvh, kb + 2 * ATILE + vo);
                ldsm4t(bvl, kb + 3 * ATILE + vo);
#pragma unroll
                for (int ns = 0; ns < 2; ns++) {
                    float* o_ = ov[dp * 2 + ns];
                    mma16816(o_, pah, &bvh[ns * 2]);
                    mma16816(o_, pal, &bvh[ns * 2]);
                    mma16816(o_, pah, &bvl[ns * 2]);
                }
            }
        }
    }

    // epilogue: normalize, split to fp16 hi/lo, write [b, s, h*64 + d]
    const float inv0 = 1.f / l0;
    const float inv1 = 1.f / l1;
    const int s0 = qt * 64 + wid * 16 + (lane >> 2);
    const size_t row0 = ((size_t)b * S + s0) * DM + h * DH;
    const size_t row1 = row0 + (size_t)8 * DM;
#pragma unroll
    for (int o = 0; o < 8; o++) {
        int d = o * 8 + (lane & 3) * 2;
        uint32_t hi0, lo0, hi1, lo1;
        split_f16(ov[o][0] * inv0, ov[o][1] * inv0, hi0, lo0);
        split_f16(ov[o][2] * inv1, ov[o][3] * inv1, hi1, lo1);
        *(uint32_t*)(AOh + row0 + d) = hi0;
        *(uint32_t*)(AOl + row0 + d) = lo0;
        *(uint32_t*)(AOh + row1 + d) = hi1;
        *(uint32_t*)(AOl + row1 + d) = lo1;
    }
}

// ---------------------------------------------------------------------------
extern "C" void kernel_launch(void* const* d_in, const int* in_sizes, int n_in,
                              void* d_out, int out_size) {
    const float* w[4] = {nullptr, nullptr, nullptr, nullptr};
    const float* x = nullptr;
    int wn = 0;
    for (int i = 0; i < n_in; i++) {
        if (in_sizes[i] == DM * DM && wn < 4) {
            w[wn++] = (const float*)d_in[i];
        } else if (in_sizes[i] == B * S * DM) {
            x = (const float*)d_in[i];
        }
    }

    __half *xhi, *xlo, *whi, *aohi, *aolo;
    __nv_bfloat16 *qkvhi, *qkvlo;
    cudaGetSymbolAddress((void**)&xhi, g_xhi);
    cudaGetSymbolAddress((void**)&xlo, g_xlo);
    cudaGetSymbolAddress((void**)&whi, g_whi);
    cudaGetSymbolAddress((void**)&qkvhi, g_qkvhi);
    cudaGetSymbolAddress((void**)&qkvlo, g_qkvlo);
    cudaGetSymbolAddress((void**)&aohi, g_aohi);
    cudaGetSymbolAddress((void**)&aolo, g_aolo);

    cudaFuncSetAttribute(gemm_f16<0>, cudaFuncAttributeMaxDynamicSharedMemorySize, GEMM_SMEM);
    cudaFuncSetAttribute(gemm_f16<1>, cudaFuncAttributeMaxDynamicSharedMemorySize, GEMM_SMEM);
    cudaFuncSetAttribute(attn_mma, cudaFuncAttributeMaxDynamicSharedMemorySize, ATT_SMEM);

    split_all<<<(SPLIT_TOTAL + 255) / 256, 256>>>(
        (const float4*)x, (const float4*)w[0], (const float4*)w[1],
        (const float4*)w[2], (const float4*)w[3],
        (uint32_t*)xhi, (uint32_t*)xlo, (uint32_t*)whi);

    dim3 qkvgrid(3 * DM / 128, M / 128);  // (24, 64)
    gemm_f16<1><<<qkvgrid, 256, GEMM_SMEM>>>(xhi, xlo, whi, nullptr, qkvhi, qkvlo);

    dim3 agrid(S / 64, H, B);  // (32, 16, 4)
    attn_mma<<<agrid, 128, ATT_SMEM>>>(qkvhi, qkvlo, aohi, aolo);

    dim3 ogrid(DM / 128, M / 128);  // (8, 64)
    gemm_f16<0><<<ogrid, 256, GEMM_SMEM>>>(aohi, aolo, whi + (size_t)3 * DM * DM,
                                           (float*)d_out, nullptr, nullptr);
}

// round 8
// speedup vs baseline: 1.0933x; 1.0407x over previous
#include <cuda_runtime.h>
#include <cuda_bf16.h>
#include <cuda_fp16.h>
#include <cstdint>
#include <math.h>

// Problem constants
constexpr int DM = 1024;   // d_model
constexpr int H  = 16;     // heads
constexpr int DH = 64;     // head dim
constexpr int B  = 4;      // batch
constexpr int S  = 2048;   // seq len
constexpr int M  = B * S;  // 8192 rows

// Scratch (allocation-free rule: __device__ globals)
__device__ __half g_xhi[(size_t)M * DM];
__device__ __half g_xlo[(size_t)M * DM];
__device__ __half g_whi[(size_t)4 * DM * DM];          // weights: fp16 RN only
__device__ __nv_bfloat16 g_qkvhi[(size_t)3 * M * DM];  // q,k,v head-major bf16
__device__ __nv_bfloat16 g_qkvlo[(size_t)3 * M * DM];
__device__ __half g_aohi[(size_t)M * DM];
__device__ __half g_aolo[(size_t)M * DM];

// ---------------------------------------------------------------------------
// PTX helpers (compute_103-safe)
// ---------------------------------------------------------------------------
__device__ __forceinline__ uint32_t smem_u32(const void* p) {
    uint32_t a;
    asm("{ .reg .u64 t; cvta.to.shared.u64 t, %1; cvt.u32.u64 %0, t; }"
        : "=r"(a) : "l"(p));
    return a;
}
__device__ __forceinline__ void cp16(uint32_t saddr, const void* gaddr) {
    asm volatile("cp.async.cg.shared.global [%0], [%1], 16;"
                 :: "r"(saddr), "l"(gaddr) : "memory");
}
__device__ __forceinline__ void cp_commit() {
    asm volatile("cp.async.commit_group;" ::: "memory");
}
template <int N>
__device__ __forceinline__ void cp_waitg() {
    asm volatile("cp.async.wait_group %0;" :: "n"(N) : "memory");
}
__device__ __forceinline__ void ldsm4(uint32_t* r, uint32_t addr) {
    asm volatile("ldmatrix.sync.aligned.m8n8.x4.shared.b16 {%0,%1,%2,%3}, [%4];"
                 : "=r"(r[0]), "=r"(r[1]), "=r"(r[2]), "=r"(r[3]) : "r"(addr));
}
__device__ __forceinline__ void ldsm4t(uint32_t* r, uint32_t addr) {
    asm volatile("ldmatrix.sync.aligned.m8n8.x4.trans.shared.b16 {%0,%1,%2,%3}, [%4];"
                 : "=r"(r[0]), "=r"(r[1]), "=r"(r[2]), "=r"(r[3]) : "r"(addr));
}
// bf16 mma (attention)
__device__ __forceinline__ void mma16816(float* c, const uint32_t* a, const uint32_t* b) {
    asm volatile(
        "mma.sync.aligned.m16n8k16.row.col.f32.bf16.bf16.f32 "
        "{%0,%1,%2,%3}, {%4,%5,%6,%7}, {%8,%9}, {%0,%1,%2,%3};"
        : "+f"(c[0]), "+f"(c[1]), "+f"(c[2]), "+f"(c[3])
        : "r"(a[0]), "r"(a[1]), "r"(a[2]), "r"(a[3]), "r"(b[0]), "r"(b[1]));
}
// fp16 mma (projection GEMMs)
__device__ __forceinline__ void mma16816h(float* c, const uint32_t* a, const uint32_t* b) {
    asm volatile(
        "mma.sync.aligned.m16n8k16.row.col.f32.f16.f16.f32 "
        "{%0,%1,%2,%3}, {%4,%5,%6,%7}, {%8,%9}, {%0,%1,%2,%3};"
        : "+f"(c[0]), "+f"(c[1]), "+f"(c[2]), "+f"(c[3])
        : "r"(a[0]), "r"(a[1]), "r"(a[2]), "r"(a[3]), "r"(b[0]), "r"(b[1]));
}
// bf16 packers (truncation hi / RN residual lo)
__device__ __forceinline__ uint32_t pk_hi2(float a, float b) {
    return __byte_perm(__float_as_uint(a), __float_as_uint(b), 0x7632);
}
__device__ __forceinline__ uint32_t pk_lo2(float a, float b) {
    float la = a - __uint_as_float(__float_as_uint(a) & 0xFFFF0000u);
    float lb = b - __uint_as_float(__float_as_uint(b) & 0xFFFF0000u);
    uint32_t r;
    asm("cvt.rn.bf16x2.f32 %0, %1, %2;" : "=r"(r) : "f"(lb), "f"(la));
    return r;
}
// fp16 RN pack (a -> low half)
__device__ __forceinline__ uint32_t pkh2(float a, float b) {
    uint32_t r;
    asm("cvt.rn.f16x2.f32 %0, %1, %2;" : "=r"(r) : "f"(b), "f"(a));
    return r;
}
// fp16 hi/lo split of a float pair
__device__ __forceinline__ void split_f16(float a, float b, uint32_t& hi, uint32_t& lo) {
    __half ha = __float2half_rn(a);
    __half hb = __float2half_rn(b);
    hi = ((uint32_t)__half_as_ushort(hb) << 16) | __half_as_ushort(ha);
    lo = pkh2(a - __half2float(ha), b - __half2float(hb));
}

// ---------------------------------------------------------------------------
// Merged split: x -> fp16 hi/lo, 4 weights -> fp16 RN. One launch.
// ---------------------------------------------------------------------------
constexpr int XN4 = (M * DM) / 4;     // 2M float4
constexpr int WN4 = (DM * DM) / 4;    // 256K float4
constexpr int SPLIT_TOTAL = XN4 + 4 * WN4;

__global__ __launch_bounds__(256) void split_all(
    const float4* __restrict__ x,
    const float4* __restrict__ w0, const float4* __restrict__ w1,
    const float4* __restrict__ w2, const float4* __restrict__ w3,
    uint32_t* __restrict__ xhi, uint32_t* __restrict__ xlo,
    uint32_t* __restrict__ whi) {
    int i = blockIdx.x * 256 + threadIdx.x;
    if (i >= SPLIT_TOTAL) return;
    if (i < XN4) {
        float4 v = x[i];
        uint32_t h0, l0, h1, l1;
        split_f16(v.x, v.y, h0, l0);
        split_f16(v.z, v.w, h1, l1);
        xhi[2 * i] = h0; xhi[2 * i + 1] = h1;
        xlo[2 * i] = l0; xlo[2 * i + 1] = l1;
    } else {
        int j = i - XN4;
        int widx = j >> 18;            // / WN4
        int wj = j & (WN4 - 1);
        const float4* ws[4] = {w0, w1, w2, w3};
        float4 v = ws[widx][wj];
        size_t o = (size_t)widx * (2 * WN4) + 2 * wj;
        whi[o]     = pkh2(v.x, v.y);
        whi[o + 1] = pkh2(v.z, v.w);
    }
}

// ---------------------------------------------------------------------------
// fp16 2-term GEMM: C[M,N] = (Ah+Al)[M,K] @ Wh[N,K]^T, fp32 accumulate.
// BM=128 BN=128 BK=32, 256 thr: 8 warps in 4x2 -> warp tile 32x64
// (16 LDSM per 64 HMMA per iter, LSU no longer binding). 3-stage cp.async,
// one barrier per k-iteration.
// OUTBF=1: fused QKV (grid.x=24, widx=bn>>3), bf16 hi/lo head-major.
// ---------------------------------------------------------------------------
constexpr int ROWB = 80;
constexpr int TILEB = 128 * ROWB;            // 10240
constexpr int A_REG = 3 * 2 * TILEB;         // 3 stages x {hi,lo}
constexpr int GEMM_SMEM = A_REG + 3 * TILEB; // + B hi (3 stages) = 92160
constexpr int NKT = DM / 32;

template <int OUTBF>
__global__ __launch_bounds__(256) void gemm_f16(const __half* __restrict__ Ah,
                                                const __half* __restrict__ Al,
                                                const __half* __restrict__ Wh,
                                                float* __restrict__ C,
                                                __nv_bfloat16* __restrict__ QKVhi,
                                                __nv_bfloat16* __restrict__ QKVlo) {
    extern __shared__ char smem[];
    const uint32_t sb = smem_u32(smem);
    const int tid = threadIdx.x;
    const int lane = tid & 31;
    const int wid = tid >> 5;
    const int warpM = wid & 3;          // 0..3 -> 32 rows each
    const int warpN = wid >> 2;         // 0..1 -> 64 cols each
    const int bn = blockIdx.x;
    const int bm = blockIdx.y;
    const int widx = (OUTBF == 1) ? (bn >> 3) : 0;
    const int bnl = (OUTBF == 1) ? (bn & 7) : bn;
    const int rowA0 = bm * 128;
    const int rowB0 = bnl * 128;
    const __half* Bh = Wh + (size_t)widx * DM * DM;

    const int lr0 = tid >> 2;
    const int lc = (tid & 3) * 8;

    auto load_stage = [&](int kt, int buf) {
        const size_t gkoff = (size_t)kt * 32 + lc;
#pragma unroll
        for (int it = 0; it < 2; it++) {
            int r = lr0 + it * 64;
            uint32_t so = (uint32_t)(r * ROWB + (tid & 3) * 16);
            size_t ga = (size_t)(rowA0 + r) * DM + gkoff;
            size_t gb = (size_t)(rowB0 + r) * DM + gkoff;
            uint32_t abase = sb + buf * 2 * TILEB;
            uint32_t bbase = sb + A_REG + buf * TILEB;
            cp16(abase + so,         Ah + ga);
            cp16(abase + TILEB + so, Al + ga);
            cp16(bbase + so,         Bh + gb);
        }
        cp_commit();
    };

    float acc[2][8][4];
#pragma unroll
    for (int i = 0; i < 2; i++)
#pragma unroll
        for (int j = 0; j < 8; j++)
#pragma unroll
            for (int e = 0; e < 4; e++) acc[i][j][e] = 0.f;

    load_stage(0, 0);
    load_stage(1, 1);

    const int a_r = (lane & 15);
    const int a_c8 = (lane >> 4) * 8;
    const int b_r = ((lane >> 4) * 8) + (lane & 7);
    const int b_c8 = ((lane >> 3) & 1) * 8;

    for (int kt = 0; kt < NKT; kt++) {
        const int buf = kt % 3;
        cp_waitg<1>();
        __syncthreads();   // data(kt) visible AND compute(kt-1) done

        int ktn = kt + 2;
        if (ktn > NKT - 1) ktn = NKT - 1;
        load_stage(ktn, (kt + 2) % 3);

        const uint32_t aHi = sb + buf * 2 * TILEB;
        const uint32_t aLo = aHi + TILEB;
        const uint32_t bHi = sb + A_REG + buf * TILEB;
        const int mrow = warpM * 32 + a_r;
        const int nrow0 = warpN * 64 + b_r;

#pragma unroll
        for (int ks = 0; ks < 2; ks++) {
            uint32_t ah[2][4], al[2][4], bh[4][4];
            const uint32_t acol = (uint32_t)((ks * 16 + a_c8) * 2);
            const uint32_t bcol = (uint32_t)((ks * 16 + b_c8) * 2);
#pragma unroll
            for (int mt = 0; mt < 2; mt++) {
                uint32_t ro = (uint32_t)((mrow + mt * 16) * ROWB) + acol;
                ldsm4(ah[mt], aHi + ro);
                ldsm4(al[mt], aLo + ro);
            }
#pragma unroll
            for (int np = 0; np < 4; np++) {
                uint32_t ro = (uint32_t)((nrow0 + np * 16) * ROWB) + bcol;
                ldsm4(bh[np], bHi + ro);
            }
#pragma unroll
            for (int mt = 0; mt < 2; mt++)
#pragma unroll
                for (int np = 0; np < 4; np++)
#pragma unroll
                    for (int ns = 0; ns < 2; ns++) {
                        float* c = acc[mt][np * 2 + ns];
                        mma16816h(c, ah[mt], &bh[np][ns * 2]);
                        mma16816h(c, al[mt], &bh[np][ns * 2]);
                    }
        }
    }

    const int rbase = bm * 128 + warpM * 32 + (lane >> 2);
    const int cbase = bnl * 128 + warpN * 64 + (lane & 3) * 2;
    __nv_bfloat16* Chi = QKVhi + (size_t)widx * M * DM;
    __nv_bfloat16* Clo = QKVlo + (size_t)widx * M * DM;
#pragma unroll
    for (int mt = 0; mt < 2; mt++) {
#pragma unroll
        for (int nt = 0; nt < 8; nt++) {
            int row = rbase + mt * 16;
            int col = cbase + nt * 8;
#pragma unroll
            for (int half = 0; half < 2; half++) {
                int r = row + half * 8;
                float vx = acc[mt][nt][half * 2];
                float vy = acc[mt][nt][half * 2 + 1];
                if (OUTBF == 0) {
                    *(float2*)(C + (size_t)r * DM + col) = make_float2(vx, vy);
                } else {
                    int b_ = r >> 11;
                    int s_ = r & 2047;
                    int h_ = col >> 6;
                    int d_ = col & 63;
                    size_t idx = ((((size_t)b_ * H + h_) * S + s_) << 6) + d_;
                    *(uint32_t*)(Chi + idx) = pk_hi2(vx, vy);
                    *(uint32_t*)(Clo + idx) = pk_lo2(vx, vy);
                }
            }
        }
    }
}

// ---------------------------------------------------------------------------
// Tensor-core causal flash attention, bf16 3-term split (128 thr,
// 64 queries/CTA). One barrier per KV tile; exp2-domain softmax.
// Writes AO as fp16 hi/lo [b, s, h*64+d].
// ---------------------------------------------------------------------------
constexpr int AROWB = 144;
constexpr int ATILE = 64 * AROWB;
constexpr int ASTG = 4 * ATILE;
constexpr int ATT_SMEM = 2 * ASTG;
constexpr float SC2 = 0.125f * 1.4426950408889634f;  // (1/sqrt(64)) * log2(e)

__global__ __launch_bounds__(128) void attn_mma(
    const __nv_bfloat16* __restrict__ QKVh, const __nv_bfloat16* __restrict__ QKVl,
    __half* __restrict__ AOh, __half* __restrict__ AOl) {
    extern __shared__ char smem[];
    const uint32_t sb = smem_u32(smem);
    const int tid = threadIdx.x;
    const int lane = tid & 31;
    const int wid = tid >> 5;
    const int qt = blockIdx.x;
    const int h = blockIdx.y;
    const int b = blockIdx.z;
    const size_t hb = (((size_t)b * H + h) * S) * DH;
    const __nv_bfloat16* Qh = QKVh;
    const __nv_bfloat16* Ql = QKVl;
    const __nv_bfloat16* Kh = QKVh + (size_t)M * DM;
    const __nv_bfloat16* Kl = QKVl + (size_t)M * DM;
    const __nv_bfloat16* Vh = QKVh + (size_t)2 * M * DM;
    const __nv_bfloat16* Vl = QKVl + (size_t)2 * M * DM;

    // Stage Q (64x64 hi/lo) into buffer 0, extract to regs
#pragma unroll
    for (int i = 0; i < 4; i++) {
        int id = tid + i * 128;
        int r = id >> 3, c = id & 7;
        uint32_t so = (uint32_t)(r * AROWB + c * 16);
        size_t g = hb + (size_t)(qt * 64 + r) * DH + c * 8;
        cp16(sb + so, Qh + g);
        cp16(sb + ATILE + so, Ql + g);
    }
    cp_commit();
    cp_waitg<0>();
    __syncthreads();

    uint32_t qh[4][4], ql[4][4];
    {
        int row = wid * 16 + (lane & 15);
#pragma unroll
        for (int ks = 0; ks < 4; ks++) {
            uint32_t off = (uint32_t)(row * AROWB + (ks * 16 + (lane >> 4) * 8) * 2);
            ldsm4(qh[ks], sb + off);
            ldsm4(ql[ks], sb + ATILE + off);
        }
    }
    __syncthreads();

    float ov[8][4];
#pragma unroll
    for (int o = 0; o < 8; o++)
#pragma unroll
        for (int e = 0; e < 4; e++) ov[o][e] = 0.f;
    float m0 = -1e30f, m1 = -1e30f, l0 = 0.f, l1 = 0.f;

    const int nkt = qt + 1;

    auto load_kv = [&](int kt, int bufi) {
        uint32_t base = sb + bufi * ASTG;
#pragma unroll
        for (int i = 0; i < 4; i++) {
            int id = tid + i * 128;
            int r = id >> 3, c = id & 7;
            uint32_t so = (uint32_t)(r * AROWB + c * 16);
            size_t g = hb + (size_t)(kt * 64 + r) * DH + c * 8;
            cp16(base + so,             Kh + g);
            cp16(base + ATILE + so,     Kl + g);
            cp16(base + 2 * ATILE + so, Vh + g);
            cp16(base + 3 * ATILE + so, Vl + g);
        }
        cp_commit();
    };
    load_kv(0, 0);

    const int q0 = qt * 64 + wid * 16 + (lane >> 2);
    const int q1 = q0 + 8;

    for (int kt = 0; kt < nkt; kt++) {
        const int buf = kt & 1;
        cp_waitg<0>();
        __syncthreads();

        if (kt + 1 < nkt) load_kv(kt + 1, buf ^ 1);

        const uint32_t kb = sb + buf * ASTG;

        // S = Qh*Kh + Ql*Kh + Qh*Kl
        float sf[8][4];
#pragma unroll
        for (int o = 0; o < 8; o++)
#pragma unroll
            for (int e = 0; e < 4; e++) sf[o][e] = 0.f;

#pragma unroll
        for (int ks = 0; ks < 4; ks++) {
#pragma unroll
            for (int np = 0; np < 4; np++) {
                uint32_t kh4[4], kl4[4];
                uint32_t ro = (uint32_t)(
                    (np * 16 + (lane >> 4) * 8 + (lane & 7)) * AROWB +
                    (ks * 16 + ((lane >> 3) & 1) * 8) * 2);
                ldsm4(kh4, kb + ro);
                ldsm4(kl4, kb + ATILE + ro);
#pragma unroll
                for (int ns = 0; ns < 2; ns++) {
                    float* c = sf[np * 2 + ns];
                    mma16816(c, qh[ks], &kh4[ns * 2]);
                    mma16816(c, qh[ks], &kl4[ns * 2]);
                    mma16816(c, ql[ks], &kh4[ns * 2]);
                }
            }
        }

        // online softmax in exp2 domain
        const bool diag = (kt == qt);
        float mx0 = -1e30f, mx1 = -1e30f;
#pragma unroll
        for (int o = 0; o < 8; o++) {
#pragma unroll
            for (int e = 0; e < 2; e++) {
                int keyl = o * 8 + (lane & 3) * 2 + e;
                float v0 = sf[o][e] * SC2;
                float v1 = sf[o][2 + e] * SC2;
                if (diag && keyl > q0 - qt * 64) v0 = -1e30f;
                if (diag && keyl > q1 - qt * 64) v1 = -1e30f;
                sf[o][e] = v0;
                sf[o][2 + e] = v1;
                mx0 = fmaxf(mx0, v0);
                mx1 = fmaxf(mx1, v1);
            }
        }
        mx0 = fmaxf(mx0, __shfl_xor_sync(0xffffffffu, mx0, 1));
        mx0 = fmaxf(mx0, __shfl_xor_sync(0xffffffffu, mx0, 2));
        mx1 = fmaxf(mx1, __shfl_xor_sync(0xffffffffu, mx1, 1));
        mx1 = fmaxf(mx1, __shfl_xor_sync(0xffffffffu, mx1, 2));
        const float mn0 = fmaxf(m0, mx0);
        const float mn1 = fmaxf(m1, mx1);
        const float es0 = exp2f(m0 - mn0);
        const float es1 = exp2f(m1 - mn1);
        m0 = mn0; m1 = mn1;

        float rs0 = 0.f, rs1 = 0.f;
#pragma unroll
        for (int o = 0; o < 8; o++) {
#pragma unroll
            for (int e = 0; e < 2; e++) {
                float p0 = exp2f(sf[o][e] - mn0);
                float p1 = exp2f(sf[o][2 + e] - mn1);
                sf[o][e] = p0;
                sf[o][2 + e] = p1;
                rs0 += p0;
                rs1 += p1;
            }
        }
        rs0 += __shfl_xor_sync(0xffffffffu, rs0, 1);
        rs0 += __shfl_xor_sync(0xffffffffu, rs0, 2);
        rs1 += __shfl_xor_sync(0xffffffffu, rs1, 1);
        rs1 += __shfl_xor_sync(0xffffffffu, rs1, 2);
        l0 = l0 * es0 + rs0;
        l1 = l1 * es1 + rs1;
#pragma unroll
        for (int o = 0; o < 8; o++) {
            ov[o][0] *= es0; ov[o][1] *= es0;
            ov[o][2] *= es1; ov[o][3] *= es1;
        }

        // O += Ph*Vh + Pl*Vh + Ph*Vl
#pragma unroll
        for (int kp = 0; kp < 4; kp++) {
            uint32_t pah[4], pal[4];
            pah[0] = pk_hi2(sf[2 * kp][0], sf[2 * kp][1]);
            pah[1] = pk_hi2(sf[2 * kp][2], sf[2 * kp][3]);
            pah[2] = pk_hi2(sf[2 * kp + 1][0], sf[2 * kp + 1][1]);
            pah[3] = pk_hi2(sf[2 * kp + 1][2], sf[2 * kp + 1][3]);
            pal[0] = pk_lo2(sf[2 * kp][0], sf[2 * kp][1]);
            pal[1] = pk_lo2(sf[2 * kp][2], sf[2 * kp][3]);
            pal[2] = pk_lo2(sf[2 * kp + 1][0], sf[2 * kp + 1][1]);
            pal[3] = pk_lo2(sf[2 * kp + 1][2], sf[2 * kp + 1][3]);
#pragma unroll
            for (int dp = 0; dp < 4; dp++) {
                uint32_t bvh[4], bvl[4];
                uint32_t vo = (uint32_t)(
                    (kp * 16 + (lane & 15)) * AROWB +
                    (dp * 16 + (lane >> 4) * 8) * 2);
                ldsm4t(bvh, kb + 2 * ATILE + vo);
                ldsm4t(bvl, kb + 3 * ATILE + vo);
#pragma unroll
                for (int ns = 0; ns < 2; ns++) {
                    float* o_ = ov[dp * 2 + ns];
                    mma16816(o_, pah, &bvh[ns * 2]);
                    mma16816(o_, pal, &bvh[ns * 2]);
                    mma16816(o_, pah, &bvl[ns * 2]);
                }
            }
        }
    }

    // epilogue: normalize, split to fp16 hi/lo, write [b, s, h*64 + d]
    const float inv0 = 1.f / l0;
    const float inv1 = 1.f / l1;
    const int s0 = qt * 64 + wid * 16 + (lane >> 2);
    const size_t row0 = ((size_t)b * S + s0) * DM + h * DH;
    const size_t row1 = row0 + (size_t)8 * DM;
#pragma unroll
    for (int o = 0; o < 8; o++) {
        int d = o * 8 + (lane & 3) * 2;
        uint32_t hi0, lo0, hi1, lo1;
        split_f16(ov[o][0] * inv0, ov[o][1] * inv0, hi0, lo0);
        split_f16(ov[o][2] * inv1, ov[o][3] * inv1, hi1, lo1);
        *(uint32_t*)(AOh + row0 + d) = hi0;
        *(uint32_t*)(AOl + row0 + d) = lo0;
        *(uint32_t*)(AOh + row1 + d) = hi1;
        *(uint32_t*)(AOl + row1 + d) = lo1;
    }
}

// ---------------------------------------------------------------------------
extern "C" void kernel_launch(void* const* d_in, const int* in_sizes, int n_in,
                              void* d_out, int out_size) {
    const float* w[4] = {nullptr, nullptr, nullptr, nullptr};
    const float* x = nullptr;
    int wn = 0;
    for (int i = 0; i < n_in; i++) {
        if (in_sizes[i] == DM * DM && wn < 4) {
            w[wn++] = (const float*)d_in[i];
        } else if (in_sizes[i] == B * S * DM) {
            x = (const float*)d_in[i];
        }
    }

    __half *xhi, *xlo, *whi, *aohi, *aolo;
    __nv_bfloat16 *qkvhi, *qkvlo;
    cudaGetSymbolAddress((void**)&xhi, g_xhi);
    cudaGetSymbolAddress((void**)&xlo, g_xlo);
    cudaGetSymbolAddress((void**)&whi, g_whi);
    cudaGetSymbolAddress((void**)&qkvhi, g_qkvhi);
    cudaGetSymbolAddress((void**)&qkvlo, g_qkvlo);
    cudaGetSymbolAddress((void**)&aohi, g_aohi);
    cudaGetSymbolAddress((void**)&aolo, g_aolo);

    cudaFuncSetAttribute(gemm_f16<0>, cudaFuncAttributeMaxDynamicSharedMemorySize, GEMM_SMEM);
    cudaFuncSetAttribute(gemm_f16<1>, cudaFuncAttributeMaxDynamicSharedMemorySize, GEMM_SMEM);
    cudaFuncSetAttribute(attn_mma, cudaFuncAttributeMaxDynamicSharedMemorySize, ATT_SMEM);

    split_all<<<(SPLIT_TOTAL + 255) / 256, 256>>>(
        (const float4*)x, (const float4*)w[0], (const float4*)w[1],
        (const float4*)w[2], (const float4*)w[3],
        (uint32_t*)xhi, (uint32_t*)xlo, (uint32_t*)whi);

    dim3 qkvgrid(3 * DM / 128, M / 128);  // (24, 64)
    gemm_f16<1><<<qkvgrid, 256, GEMM_SMEM>>>(xhi, xlo, whi, nullptr, qkvhi, qkvlo);

    dim3 agrid(S / 64, H, B);  // (32, 16, 4)
    attn_mma<<<agrid, 128, ATT_SMEM>>>(qkvhi, qkvlo, aohi, aolo);

    dim3 ogrid(DM / 128, M / 128);  // (8, 64)
    gemm_f16<0><<<ogrid, 256, GEMM_SMEM>>>(aohi, aolo, whi + (size_t)3 * DM * DM,
                                           (float*)d_out, nullptr, nullptr);
}

// round 9
// speedup vs baseline: 1.3868x; 1.2685x over previous
#include <cuda_runtime.h>
#include <cuda_bf16.h>
#include <cuda_fp16.h>
#include <cstdint>
#include <math.h>

// Problem constants
constexpr int DM = 1024;   // d_model
constexpr int H  = 16;     // heads
constexpr int DH = 64;     // head dim
constexpr int B  = 4;      // batch
constexpr int S  = 2048;   // seq len
constexpr int M  = B * S;  // 8192 rows

// Scratch (allocation-free rule: __device__ globals)
__device__ __half g_xh[(size_t)M * DM];                // x, fp16 RN
__device__ __half g_whi[(size_t)4 * DM * DM];          // weights, fp16 RN
__device__ __nv_bfloat16 g_qkvhi[(size_t)3 * M * DM];  // q,k,v head-major bf16 hi
__device__ __nv_bfloat16 g_qkvlo[(size_t)3 * M * DM];  // q,k,v head-major bf16 lo
__device__ __half g_aoh[(size_t)M * DM];               // attention out, fp16 RN

// ---------------------------------------------------------------------------
// PTX helpers (compute_103-safe)
// ---------------------------------------------------------------------------
__device__ __forceinline__ uint32_t smem_u32(const void* p) {
    uint32_t a;
    asm("{ .reg .u64 t; cvta.to.shared.u64 t, %1; cvt.u32.u64 %0, t; }"
        : "=r"(a) : "l"(p));
    return a;
}
__device__ __forceinline__ void cp16(uint32_t saddr, const void* gaddr) {
    asm volatile("cp.async.cg.shared.global [%0], [%1], 16;"
                 :: "r"(saddr), "l"(gaddr) : "memory");
}
__device__ __forceinline__ void cp_commit() {
    asm volatile("cp.async.commit_group;" ::: "memory");
}
template <int N>
__device__ __forceinline__ void cp_waitg() {
    asm volatile("cp.async.wait_group %0;" :: "n"(N) : "memory");
}
__device__ __forceinline__ void ldsm4(uint32_t* r, uint32_t addr) {
    asm volatile("ldmatrix.sync.aligned.m8n8.x4.shared.b16 {%0,%1,%2,%3}, [%4];"
                 : "=r"(r[0]), "=r"(r[1]), "=r"(r[2]), "=r"(r[3]) : "r"(addr));
}
__device__ __forceinline__ void ldsm4t(uint32_t* r, uint32_t addr) {
    asm volatile("ldmatrix.sync.aligned.m8n8.x4.trans.shared.b16 {%0,%1,%2,%3}, [%4];"
                 : "=r"(r[0]), "=r"(r[1]), "=r"(r[2]), "=r"(r[3]) : "r"(addr));
}
// bf16 mma (attention)
__device__ __forceinline__ void mma16816(float* c, const uint32_t* a, const uint32_t* b) {
    asm volatile(
        "mma.sync.aligned.m16n8k16.row.col.f32.bf16.bf16.f32 "
        "{%0,%1,%2,%3}, {%4,%5,%6,%7}, {%8,%9}, {%0,%1,%2,%3};"
        : "+f"(c[0]), "+f"(c[1]), "+f"(c[2]), "+f"(c[3])
        : "r"(a[0]), "r"(a[1]), "r"(a[2]), "r"(a[3]), "r"(b[0]), "r"(b[1]));
}
// fp16 mma (projection GEMMs)
__device__ __forceinline__ void mma16816h(float* c, const uint32_t* a, const uint32_t* b) {
    asm volatile(
        "mma.sync.aligned.m16n8k16.row.col.f32.f16.f16.f32 "
        "{%0,%1,%2,%3}, {%4,%5,%6,%7}, {%8,%9}, {%0,%1,%2,%3};"
        : "+f"(c[0]), "+f"(c[1]), "+f"(c[2]), "+f"(c[3])
        : "r"(a[0]), "r"(a[1]), "r"(a[2]), "r"(a[3]), "r"(b[0]), "r"(b[1]));
}
// bf16 packers (truncation hi / RN residual lo)
__device__ __forceinline__ uint32_t pk_hi2(float a, float b) {
    return __byte_perm(__float_as_uint(a), __float_as_uint(b), 0x7632);
}
__device__ __forceinline__ uint32_t pk_lo2(float a, float b) {
    float la = a - __uint_as_float(__float_as_uint(a) & 0xFFFF0000u);
    float lb = b - __uint_as_float(__float_as_uint(b) & 0xFFFF0000u);
    uint32_t r;
    asm("cvt.rn.bf16x2.f32 %0, %1, %2;" : "=r"(r) : "f"(lb), "f"(la));
    return r;
}
// fp16 RN pack (a -> low half)
__device__ __forceinline__ uint32_t pkh2(float a, float b) {
    uint32_t r;
    asm("cvt.rn.f16x2.f32 %0, %1, %2;" : "=r"(r) : "f"(b), "f"(a));
    return r;
}

// ---------------------------------------------------------------------------
// Merged split: x -> fp16 RN, 4 weights -> fp16 RN. One launch.
// ---------------------------------------------------------------------------
constexpr int XN4 = (M * DM) / 4;     // 2M float4
constexpr int WN4 = (DM * DM) / 4;    // 256K float4
constexpr int SPLIT_TOTAL = XN4 + 4 * WN4;

__global__ __launch_bounds__(256) void split_all(
    const float4* __restrict__ x,
    const float4* __restrict__ w0, const float4* __restrict__ w1,
    const float4* __restrict__ w2, const float4* __restrict__ w3,
    uint32_t* __restrict__ xh, uint32_t* __restrict__ whi) {
    int i = blockIdx.x * 256 + threadIdx.x;
    if (i >= SPLIT_TOTAL) return;
    if (i < XN4) {
        float4 v = x[i];
        xh[2 * i]     = pkh2(v.x, v.y);
        xh[2 * i + 1] = pkh2(v.z, v.w);
    } else {
        int j = i - XN4;
        int widx = j >> 18;            // / WN4
        int wj = j & (WN4 - 1);
        const float4* ws[4] = {w0, w1, w2, w3};
        float4 v = ws[widx][wj];
        size_t o = (size_t)widx * (2 * WN4) + 2 * wj;
        whi[o]     = pkh2(v.x, v.y);
        whi[o + 1] = pkh2(v.z, v.w);
    }
}

// ---------------------------------------------------------------------------
// fp16 single-term GEMM: C[M,N] = Ah[M,K] @ Wh[N,K]^T, fp32 accumulate.
// BM=128 BN=128 BK=32, 256 thr: 8 warps 4x2 -> warp tile 32x64.
// 4-stage cp.async pipeline (prefetch distance 3), one barrier per k-iter.
// OUTBF=1: fused QKV (grid.x=24, widx=bn>>3), bf16 hi/lo head-major out.
// ---------------------------------------------------------------------------
constexpr int ROWB = 80;
constexpr int TILEB = 128 * ROWB;            // 10240
constexpr int NSTG = 4;
constexpr int A_REG = NSTG * TILEB;          // 40960
constexpr int GEMM_SMEM = 2 * A_REG;         // A + B regions = 81920
constexpr int NKT = DM / 32;

template <int OUTBF>
__global__ __launch_bounds__(256) void gemm_f16(const __half* __restrict__ Ah,
                                                const __half* __restrict__ Wh,
                                                float* __restrict__ C,
                                                __nv_bfloat16* __restrict__ QKVhi,
                                                __nv_bfloat16* __restrict__ QKVlo) {
    extern __shared__ char smem[];
    const uint32_t sb = smem_u32(smem);
    const int tid = threadIdx.x;
    const int lane = tid & 31;
    const int wid = tid >> 5;
    const int warpM = wid & 3;          // 0..3 -> 32 rows each
    const int warpN = wid >> 2;         // 0..1 -> 64 cols each
    const int bn = blockIdx.x;
    const int bm = blockIdx.y;
    const int widx = (OUTBF == 1) ? (bn >> 3) : 0;
    const int bnl = (OUTBF == 1) ? (bn & 7) : bn;
    const int rowA0 = bm * 128;
    const int rowB0 = bnl * 128;
    const __half* Bh = Wh + (size_t)widx * DM * DM;

    const int lr0 = tid >> 2;
    const int lc = (tid & 3) * 8;

    auto load_stage = [&](int kt, int buf) {
        const size_t gkoff = (size_t)kt * 32 + lc;
#pragma unroll
        for (int it = 0; it < 2; it++) {
            int r = lr0 + it * 64;
            uint32_t so = (uint32_t)(r * ROWB + (tid & 3) * 16);
            size_t ga = (size_t)(rowA0 + r) * DM + gkoff;
            size_t gb = (size_t)(rowB0 + r) * DM + gkoff;
            cp16(sb + buf * TILEB + so,         Ah + ga);
            cp16(sb + A_REG + buf * TILEB + so, Bh + gb);
        }
        cp_commit();
    };

    float acc[2][8][4];
#pragma unroll
    for (int i = 0; i < 2; i++)
#pragma unroll
        for (int j = 0; j < 8; j++)
#pragma unroll
            for (int e = 0; e < 4; e++) acc[i][j][e] = 0.f;

    load_stage(0, 0);
    load_stage(1, 1);
    load_stage(2, 2);

    const int a_r = (lane & 15);
    const int a_c8 = (lane >> 4) * 8;
    const int b_r = ((lane >> 4) * 8) + (lane & 7);
    const int b_c8 = ((lane >> 3) & 1) * 8;

    for (int kt = 0; kt < NKT; kt++) {
        const int buf = kt & 3;
        cp_waitg<2>();
        __syncthreads();   // data(kt) visible AND compute(kt-1) done

        int ktn = kt + 3;
        if (ktn > NKT - 1) ktn = NKT - 1;
        load_stage(ktn, (kt + 3) & 3);

        const uint32_t aHi = sb + buf * TILEB;
        const uint32_t bHi = sb + A_REG + buf * TILEB;
        const int mrow = warpM * 32 + a_r;
        const int nrow0 = warpN * 64 + b_r;

#pragma unroll
        for (int ks = 0; ks < 2; ks++) {
            uint32_t ah[2][4], bh[4][4];
            const uint32_t acol = (uint32_t)((ks * 16 + a_c8) * 2);
            const uint32_t bcol = (uint32_t)((ks * 16 + b_c8) * 2);
#pragma unroll
            for (int mt = 0; mt < 2; mt++) {
                uint32_t ro = (uint32_t)((mrow + mt * 16) * ROWB) + acol;
                ldsm4(ah[mt], aHi + ro);
            }
#pragma unroll
            for (int np = 0; np < 4; np++) {
                uint32_t ro = (uint32_t)((nrow0 + np * 16) * ROWB) + bcol;
                ldsm4(bh[np], bHi + ro);
            }
#pragma unroll
            for (int mt = 0; mt < 2; mt++)
#pragma unroll
                for (int np = 0; np < 4; np++)
#pragma unroll
                    for (int ns = 0; ns < 2; ns++)
                        mma16816h(acc[mt][np * 2 + ns], ah[mt], &bh[np][ns * 2]);
        }
    }

    const int rbase = bm * 128 + warpM * 32 + (lane >> 2);
    const int cbase = bnl * 128 + warpN * 64 + (lane & 3) * 2;
    __nv_bfloat16* Chi = QKVhi + (size_t)widx * M * DM;
    __nv_bfloat16* Clo = QKVlo + (size_t)widx * M * DM;
#pragma unroll
    for (int mt = 0; mt < 2; mt++) {
#pragma unroll
        for (int nt = 0; nt < 8; nt++) {
            int row = rbase + mt * 16;
            int col = cbase + nt * 8;
#pragma unroll
            for (int half = 0; half < 2; half++) {
                int r = row + half * 8;
                float vx = acc[mt][nt][half * 2];
                float vy = acc[mt][nt][half * 2 + 1];
                if (OUTBF == 0) {
                    *(float2*)(C + (size_t)r * DM + col) = make_float2(vx, vy);
                } else {
                    int b_ = r >> 11;
                    int s_ = r & 2047;
                    int h_ = col >> 6;
                    int d_ = col & 63;
                    size_t idx = ((((size_t)b_ * H + h_) * S + s_) << 6) + d_;
                    *(uint32_t*)(Chi + idx) = pk_hi2(vx, vy);
                    *(uint32_t*)(Clo + idx) = pk_lo2(vx, vy);
                }
            }
        }
    }
}

// ---------------------------------------------------------------------------
// Tensor-core causal flash attention, bf16 3-term split (128 thr,
// 64 queries/CTA). One barrier per KV tile; exp2-domain softmax.
// Writes AO as fp16 RN [b, s, h*64+d].
// ---------------------------------------------------------------------------
constexpr int AROWB = 144;
constexpr int ATILE = 64 * AROWB;
constexpr int ASTG = 4 * ATILE;
constexpr int ATT_SMEM = 2 * ASTG;
constexpr float SC2 = 0.125f * 1.4426950408889634f;  // (1/sqrt(64)) * log2(e)

__global__ __launch_bounds__(128) void attn_mma(
    const __nv_bfloat16* __restrict__ QKVh, const __nv_bfloat16* __restrict__ QKVl,
    __half* __restrict__ AOh) {
    extern __shared__ char smem[];
    const uint32_t sb = smem_u32(smem);
    const int tid = threadIdx.x;
    const int lane = tid & 31;
    const int wid = tid >> 5;
    const int qt = blockIdx.x;
    const int h = blockIdx.y;
    const int b = blockIdx.z;
    const size_t hb = (((size_t)b * H + h) * S) * DH;
    const __nv_bfloat16* Qh = QKVh;
    const __nv_bfloat16* Ql = QKVl;
    const __nv_bfloat16* Kh = QKVh + (size_t)M * DM;
    const __nv_bfloat16* Kl = QKVl + (size_t)M * DM;
    const __nv_bfloat16* Vh = QKVh + (size_t)2 * M * DM;
    const __nv_bfloat16* Vl = QKVl + (size_t)2 * M * DM;

    // Stage Q (64x64 hi/lo) into buffer 0, extract to regs
#pragma unroll
    for (int i = 0; i < 4; i++) {
        int id = tid + i * 128;
        int r = id >> 3, c = id & 7;
        uint32_t so = (uint32_t)(r * AROWB + c * 16);
        size_t g = hb + (size_t)(qt * 64 + r) * DH + c * 8;
        cp16(sb + so, Qh + g);
        cp16(sb + ATILE + so, Ql + g);
    }
    cp_commit();
    cp_waitg<0>();
    __syncthreads();

    uint32_t qh[4][4], ql[4][4];
    {
        int row = wid * 16 + (lane & 15);
#pragma unroll
        for (int ks = 0; ks < 4; ks++) {
            uint32_t off = (uint32_t)(row * AROWB + (ks * 16 + (lane >> 4) * 8) * 2);
            ldsm4(qh[ks], sb + off);
            ldsm4(ql[ks], sb + ATILE + off);
        }
    }
    __syncthreads();

    float ov[8][4];
#pragma unroll
    for (int o = 0; o < 8; o++)
#pragma unroll
        for (int e = 0; e < 4; e++) ov[o][e] = 0.f;
    float m0 = -1e30f, m1 = -1e30f, l0 = 0.f, l1 = 0.f;

    const int nkt = qt + 1;

    auto load_kv = [&](int kt, int bufi) {
        uint32_t base = sb + bufi * ASTG;
#pragma unroll
        for (int i = 0; i < 4; i++) {
            int id = tid + i * 128;
            int r = id >> 3, c = id & 7;
            uint32_t so = (uint32_t)(r * AROWB + c * 16);
            size_t g = hb + (size_t)(kt * 64 + r) * DH + c * 8;
            cp16(base + so,             Kh + g);
            cp16(base + ATILE + so,     Kl + g);
            cp16(base + 2 * ATILE + so, Vh + g);
            cp16(base + 3 * ATILE + so, Vl + g);
        }
        cp_commit();
    };
    load_kv(0, 0);

    const int q0 = qt * 64 + wid * 16 + (lane >> 2);
    const int q1 = q0 + 8;

    for (int kt = 0; kt < nkt; kt++) {
        const int buf = kt & 1;
        cp_waitg<0>();
        __syncthreads();

        if (kt + 1 < nkt) load_kv(kt + 1, buf ^ 1);

        const uint32_t kb = sb + buf * ASTG;

        // S = Qh*Kh + Ql*Kh + Qh*Kl
        float sf[8][4];
#pragma unroll
        for (int o = 0; o < 8; o++)
#pragma unroll
            for (int e = 0; e < 4; e++) sf[o][e] = 0.f;

#pragma unroll
        for (int ks = 0; ks < 4; ks++) {
#pragma unroll
            for (int np = 0; np < 4; np++) {
                uint32_t kh4[4], kl4[4];
                uint32_t ro = (uint32_t)(
                    (np * 16 + (lane >> 4) * 8 + (lane & 7)) * AROWB +
                    (ks * 16 + ((lane >> 3) & 1) * 8) * 2);
                ldsm4(kh4, kb + ro);
                ldsm4(kl4, kb + ATILE + ro);
#pragma unroll
                for (int ns = 0; ns < 2; ns++) {
                    float* c = sf[np * 2 + ns];
                    mma16816(c, qh[ks], &kh4[ns * 2]);
                    mma16816(c, qh[ks], &kl4[ns * 2]);
                    mma16816(c, ql[ks], &kh4[ns * 2]);
                }
            }
        }

        // online softmax in exp2 domain
        const bool diag = (kt == qt);
        float mx0 = -1e30f, mx1 = -1e30f;
#pragma unroll
        for (int o = 0; o < 8; o++) {
#pragma unroll
            for (int e = 0; e < 2; e++) {
                int keyl = o * 8 + (lane & 3) * 2 + e;
                float v0 = sf[o][e] * SC2;
                float v1 = sf[o][2 + e] * SC2;
                if (diag && keyl > q0 - qt * 64) v0 = -1e30f;
                if (diag && keyl > q1 - qt * 64) v1 = -1e30f;
                sf[o][e] = v0;
                sf[o][2 + e] = v1;
                mx0 = fmaxf(mx0, v0);
                mx1 = fmaxf(mx1, v1);
            }
        }
        mx0 = fmaxf(mx0, __shfl_xor_sync(0xffffffffu, mx0, 1));
        mx0 = fmaxf(mx0, __shfl_xor_sync(0xffffffffu, mx0, 2));
        mx1 = fmaxf(mx1, __shfl_xor_sync(0xffffffffu, mx1, 1));
        mx1 = fmaxf(mx1, __shfl_xor_sync(0xffffffffu, mx1, 2));
        const float mn0 = fmaxf(m0, mx0);
        const float mn1 = fmaxf(m1, mx1);
        const float es0 = exp2f(m0 - mn0);
        const float es1 = exp2f(m1 - mn1);
        m0 = mn0; m1 = mn1;

        float rs0 = 0.f, rs1 = 0.f;
#pragma unroll
        for (int o = 0; o < 8; o++) {
#pragma unroll
            for (int e = 0; e < 2; e++) {
                float p0 = exp2f(sf[o][e] - mn0);
                float p1 = exp2f(sf[o][2 + e] - mn1);
                sf[o][e] = p0;
                sf[o][2 + e] = p1;
                rs0 += p0;
                rs1 += p1;
            }
        }
        rs0 += __shfl_xor_sync(0xffffffffu, rs0, 1);
        rs0 += __shfl_xor_sync(0xffffffffu, rs0, 2);
        rs1 += __shfl_xor_sync(0xffffffffu, rs1, 1);
        rs1 += __shfl_xor_sync(0xffffffffu, rs1, 2);
        l0 = l0 * es0 + rs0;
        l1 = l1 * es1 + rs1;
#pragma unroll
        for (int o = 0; o < 8; o++) {
            ov[o][0] *= es0; ov[o][1] *= es0;
            ov[o][2] *= es1; ov[o][3] *= es1;
        }

        // O += Ph*Vh + Pl*Vh + Ph*Vl
#pragma unroll
        for (int kp = 0; kp < 4; kp++) {
            uint32_t pah[4], pal[4];
            pah[0] = pk_hi2(sf[2 * kp][0], sf[2 * kp][1]);
            pah[1] = pk_hi2(sf[2 * kp][2], sf[2 * kp][3]);
            pah[2] = pk_hi2(sf[2 * kp + 1][0], sf[2 * kp + 1][1]);
            pah[3] = pk_hi2(sf[2 * kp + 1][2], sf[2 * kp + 1][3]);
            pal[0] = pk_lo2(sf[2 * kp][0], sf[2 * kp][1]);
            pal[1] = pk_lo2(sf[2 * kp][2], sf[2 * kp][3]);
            pal[2] = pk_lo2(sf[2 * kp + 1][0], sf[2 * kp + 1][1]);
            pal[3] = pk_lo2(sf[2 * kp + 1][2], sf[2 * kp + 1][3]);
#pragma unroll
            for (int dp = 0; dp < 4; dp++) {
                uint32_t bvh[4], bvl[4];
                uint32_t vo = (uint32_t)(
                    (kp * 16 + (lane & 15)) * AROWB +
                    (dp * 16 + (lane >> 4) * 8) * 2);
                ldsm4t(bvh, kb + 2 * ATILE + vo);
                ldsm4t(bvl, kb + 3 * ATILE + vo);
#pragma unroll
                for (int ns = 0; ns < 2; ns++) {
                    float* o_ = ov[dp * 2 + ns];
                    mma16816(o_, pah, &bvh[ns * 2]);
                    mma16816(o_, pal, &bvh[ns * 2]);
                    mma16816(o_, pah, &bvl[ns * 2]);
                }
            }
        }
    }

    // epilogue: normalize, fp16 RN, write [b, s, h*64 + d]
    const float inv0 = 1.f / l0;
    const float inv1 = 1.f / l1;
    const int s0 = qt * 64 + wid * 16 + (lane >> 2);
    const size_t row0 = ((size_t)b * S + s0) * DM + h * DH;
    const size_t row1 = row0 + (size_t)8 * DM;
#pragma unroll
    for (int o = 0; o < 8; o++) {
        int d = o * 8 + (lane & 3) * 2;
        *(uint32_t*)(AOh + row0 + d) = pkh2(ov[o][0] * inv0, ov[o][1] * inv0);
        *(uint32_t*)(AOh + row1 + d) = pkh2(ov[o][2] * inv1, ov[o][3] * inv1);
    }
}

// ---------------------------------------------------------------------------
extern "C" void kernel_launch(void* const* d_in, const int* in_sizes, int n_in,
                              void* d_out, int out_size) {
    const float* w[4] = {nullptr, nullptr, nullptr, nullptr};
    const float* x = nullptr;
    int wn = 0;
    for (int i = 0; i < n_in; i++) {
        if (in_sizes[i] == DM * DM && wn < 4) {
            w[wn++] = (const float*)d_in[i];
        } else if (in_sizes[i] == B * S * DM) {
            x = (const float*)d_in[i];
        }
    }

    __half *xh, *whi, *aoh;
    __nv_bfloat16 *qkvhi, *qkvlo;
    cudaGetSymbolAddress((void**)&xh, g_xh);
    cudaGetSymbolAddress((void**)&whi, g_whi);
    cudaGetSymbolAddress((void**)&qkvhi, g_qkvhi);
    cudaGetSymbolAddress((void**)&qkvlo, g_qkvlo);
    cudaGetSymbolAddress((void**)&aoh, g_aoh);

    cudaFuncSetAttribute(gemm_f16<0>, cudaFuncAttributeMaxDynamicSharedMemorySize, GEMM_SMEM);
    cudaFuncSetAttribute(gemm_f16<1>, cudaFuncAttributeMaxDynamicSharedMemorySize, GEMM_SMEM);
    cudaFuncSetAttribute(attn_mma, cudaFuncAttributeMaxDynamicSharedMemorySize, ATT_SMEM);

    split_all<<<(SPLIT_TOTAL + 255) / 256, 256>>>(
        (const float4*)x, (const float4*)w[0], (const float4*)w[1],
        (const float4*)w[2], (const float4*)w[3],
        (uint32_t*)xh, (uint32_t*)whi);

    dim3 qkvgrid(3 * DM / 128, M / 128);  // (24, 64)
    gemm_f16<1><<<qkvgrid, 256, GEMM_SMEM>>>(xh, whi, nullptr, qkvhi, qkvlo);

    dim3 agrid(S / 64, H, B);  // (32, 16, 4)
    attn_mma<<<agrid, 128, ATT_SMEM>>>(qkvhi, qkvlo, aoh);

    dim3 ogrid(DM / 128, M / 128);  // (8, 64)
    gemm_f16<0><<<ogrid, 256, GEMM_SMEM>>>(aoh, whi + (size_t)3 * DM * DM,
                                           (float*)d_out, nullptr, nullptr);
}

// round 10
// speedup vs baseline: 1.5742x; 1.1351x over previous
#include <cuda_runtime.h>
#include <cuda_bf16.h>
#include <cuda_fp16.h>
#include <cstdint>
#include <math.h>

// Problem constants
constexpr int DM = 1024;   // d_model
constexpr int H  = 16;     // heads
constexpr int DH = 64;     // head dim
constexpr int B  = 4;      // batch
constexpr int S  = 2048;   // seq len
constexpr int M  = B * S;  // 8192 rows

// Scratch (allocation-free rule: __device__ globals)
__device__ __half g_xh[(size_t)M * DM];                // x, fp16 RN
__device__ __half g_whi[(size_t)4 * DM * DM];          // weights, fp16 RN
__device__ __half g_qkvh[(size_t)3 * M * DM];          // q,k,v head-major fp16 hi
__device__ __half g_qlo[(size_t)M * DM];               // q lo residual (fp16)
__device__ __half g_aoh[(size_t)M * DM];               // attention out, fp16 RN

// ---------------------------------------------------------------------------
// PTX helpers (compute_103-safe)
// ---------------------------------------------------------------------------
__device__ __forceinline__ uint32_t smem_u32(const void* p) {
    uint32_t a;
    asm("{ .reg .u64 t; cvta.to.shared.u64 t, %1; cvt.u32.u64 %0, t; }"
        : "=r"(a) : "l"(p));
    return a;
}
__device__ __forceinline__ void cp16(uint32_t saddr, const void* gaddr) {
    asm volatile("cp.async.cg.shared.global [%0], [%1], 16;"
                 :: "r"(saddr), "l"(gaddr) : "memory");
}
__device__ __forceinline__ void cp_commit() {
    asm volatile("cp.async.commit_group;" ::: "memory");
}
template <int N>
__device__ __forceinline__ void cp_waitg() {
    asm volatile("cp.async.wait_group %0;" :: "n"(N) : "memory");
}
__device__ __forceinline__ void ldsm4(uint32_t* r, uint32_t addr) {
    asm volatile("ldmatrix.sync.aligned.m8n8.x4.shared.b16 {%0,%1,%2,%3}, [%4];"
                 : "=r"(r[0]), "=r"(r[1]), "=r"(r[2]), "=r"(r[3]) : "r"(addr));
}
__device__ __forceinline__ void ldsm4t(uint32_t* r, uint32_t addr) {
    asm volatile("ldmatrix.sync.aligned.m8n8.x4.trans.shared.b16 {%0,%1,%2,%3}, [%4];"
                 : "=r"(r[0]), "=r"(r[1]), "=r"(r[2]), "=r"(r[3]) : "r"(addr));
}
// fp16 mma
__device__ __forceinline__ void mma16816h(float* c, const uint32_t* a, const uint32_t* b) {
    asm volatile(
        "mma.sync.aligned.m16n8k16.row.col.f32.f16.f16.f32 "
        "{%0,%1,%2,%3}, {%4,%5,%6,%7}, {%8,%9}, {%0,%1,%2,%3};"
        : "+f"(c[0]), "+f"(c[1]), "+f"(c[2]), "+f"(c[3])
        : "r"(a[0]), "r"(a[1]), "r"(a[2]), "r"(a[3]), "r"(b[0]), "r"(b[1]));
}
// fp16 RN pack (a -> low half)
__device__ __forceinline__ uint32_t pkh2(float a, float b) {
    uint32_t r;
    asm("cvt.rn.f16x2.f32 %0, %1, %2;" : "=r"(r) : "f"(b), "f"(a));
    return r;
}
// fp16 hi/lo split of a float pair
__device__ __forceinline__ void split_f16(float a, float b, uint32_t& hi, uint32_t& lo) {
    __half ha = __float2half_rn(a);
    __half hb = __float2half_rn(b);
    hi = ((uint32_t)__half_as_ushort(hb) << 16) | __half_as_ushort(ha);
    lo = pkh2(a - __half2float(ha), b - __half2float(hb));
}

// ---------------------------------------------------------------------------
// Merged split: x -> fp16 RN, 4 weights -> fp16 RN. One launch.
// ---------------------------------------------------------------------------
constexpr int XN4 = (M * DM) / 4;     // 2M float4
constexpr int WN4 = (DM * DM) / 4;    // 256K float4
constexpr int SPLIT_TOTAL = XN4 + 4 * WN4;

__global__ __launch_bounds__(256) void split_all(
    const float4* __restrict__ x,
    const float4* __restrict__ w0, const float4* __restrict__ w1,
    const float4* __restrict__ w2, const float4* __restrict__ w3,
    uint32_t* __restrict__ xh, uint32_t* __restrict__ whi) {
    int i = blockIdx.x * 256 + threadIdx.x;
    if (i >= SPLIT_TOTAL) return;
    if (i < XN4) {
        float4 v = x[i];
        xh[2 * i]     = pkh2(v.x, v.y);
        xh[2 * i + 1] = pkh2(v.z, v.w);
    } else {
        int j = i - XN4;
        int widx = j >> 18;            // / WN4
        int wj = j & (WN4 - 1);
        const float4* ws[4] = {w0, w1, w2, w3};
        float4 v = ws[widx][wj];
        size_t o = (size_t)widx * (2 * WN4) + 2 * wj;
        whi[o]     = pkh2(v.x, v.y);
        whi[o + 1] = pkh2(v.z, v.w);
    }
}

// ---------------------------------------------------------------------------
// fp16 single-term GEMM: C[M,N] = Ah[M,K] @ Wh[N,K]^T, fp32 accumulate.
// BM=128 BN=128 BK=32, 256 thr: 8 warps 4x2 -> warp tile 32x64.
// 4-stage cp.async pipeline, one barrier per k-iter.
// OUTBF=1: fused QKV (grid.x=24, widx=bn>>3), fp16 head-major out
//          (hi for q/k/v; lo residual only for q, widx==0).
// ---------------------------------------------------------------------------
constexpr int ROWB = 80;
constexpr int TILEB = 128 * ROWB;            // 10240
constexpr int NSTG = 4;
constexpr int A_REG = NSTG * TILEB;          // 40960
constexpr int GEMM_SMEM = 2 * A_REG;         // 81920
constexpr int NKT = DM / 32;

template <int OUTBF>
__global__ __launch_bounds__(256) void gemm_f16(const __half* __restrict__ Ah,
                                                const __half* __restrict__ Wh,
                                                float* __restrict__ C,
                                                __half* __restrict__ QKVh,
                                                __half* __restrict__ Qlo) {
    extern __shared__ char smem[];
    const uint32_t sb = smem_u32(smem);
    const int tid = threadIdx.x;
    const int lane = tid & 31;
    const int wid = tid >> 5;
    const int warpM = wid & 3;
    const int warpN = wid >> 2;
    const int bn = blockIdx.x;
    const int bm = blockIdx.y;
    const int widx = (OUTBF == 1) ? (bn >> 3) : 0;
    const int bnl = (OUTBF == 1) ? (bn & 7) : bn;
    const int rowA0 = bm * 128;
    const int rowB0 = bnl * 128;
    const __half* Bh = Wh + (size_t)widx * DM * DM;

    const int lr0 = tid >> 2;
    const int lc = (tid & 3) * 8;

    auto load_stage = [&](int kt, int buf) {
        const size_t gkoff = (size_t)kt * 32 + lc;
#pragma unroll
        for (int it = 0; it < 2; it++) {
            int r = lr0 + it * 64;
            uint32_t so = (uint32_t)(r * ROWB + (tid & 3) * 16);
            size_t ga = (size_t)(rowA0 + r) * DM + gkoff;
            size_t gb = (size_t)(rowB0 + r) * DM + gkoff;
            cp16(sb + buf * TILEB + so,         Ah + ga);
            cp16(sb + A_REG + buf * TILEB + so, Bh + gb);
        }
        cp_commit();
    };

    float acc[2][8][4];
#pragma unroll
    for (int i = 0; i < 2; i++)
#pragma unroll
        for (int j = 0; j < 8; j++)
#pragma unroll
            for (int e = 0; e < 4; e++) acc[i][j][e] = 0.f;

    load_stage(0, 0);
    load_stage(1, 1);
    load_stage(2, 2);

    const int a_r = (lane & 15);
    const int a_c8 = (lane >> 4) * 8;
    const int b_r = ((lane >> 4) * 8) + (lane & 7);
    const int b_c8 = ((lane >> 3) & 1) * 8;

    for (int kt = 0; kt < NKT; kt++) {
        const int buf = kt & 3;
        cp_waitg<2>();
        __syncthreads();

        int ktn = kt + 3;
        if (ktn > NKT - 1) ktn = NKT - 1;
        load_stage(ktn, (kt + 3) & 3);

        const uint32_t aHi = sb + buf * TILEB;
        const uint32_t bHi = sb + A_REG + buf * TILEB;
        const int mrow = warpM * 32 + a_r;
        const int nrow0 = warpN * 64 + b_r;

#pragma unroll
        for (int ks = 0; ks < 2; ks++) {
            uint32_t ah[2][4], bh[4][4];
            const uint32_t acol = (uint32_t)((ks * 16 + a_c8) * 2);
            const uint32_t bcol = (uint32_t)((ks * 16 + b_c8) * 2);
#pragma unroll
            for (int mt = 0; mt < 2; mt++) {
                uint32_t ro = (uint32_t)((mrow + mt * 16) * ROWB) + acol;
                ldsm4(ah[mt], aHi + ro);
            }
#pragma unroll
            for (int np = 0; np < 4; np++) {
                uint32_t ro = (uint32_t)((nrow0 + np * 16) * ROWB) + bcol;
                ldsm4(bh[np], bHi + ro);
            }
#pragma unroll
            for (int mt = 0; mt < 2; mt++)
#pragma unroll
                for (int np = 0; np < 4; np++)
#pragma unroll
                    for (int ns = 0; ns < 2; ns++)
                        mma16816h(acc[mt][np * 2 + ns], ah[mt], &bh[np][ns * 2]);
        }
    }

    const int rbase = bm * 128 + warpM * 32 + (lane >> 2);
    const int cbase = bnl * 128 + warpN * 64 + (lane & 3) * 2;
    __half* Chi = QKVh + (size_t)widx * M * DM;
#pragma unroll
    for (int mt = 0; mt < 2; mt++) {
#pragma unroll
        for (int nt = 0; nt < 8; nt++) {
            int row = rbase + mt * 16;
            int col = cbase + nt * 8;
#pragma unroll
            for (int half = 0; half < 2; half++) {
                int r = row + half * 8;
                float vx = acc[mt][nt][half * 2];
                float vy = acc[mt][nt][half * 2 + 1];
                if (OUTBF == 0) {
                    *(float2*)(C + (size_t)r * DM + col) = make_float2(vx, vy);
                } else {
                    int b_ = r >> 11;
                    int s_ = r & 2047;
                    int h_ = col >> 6;
                    int d_ = col & 63;
                    size_t idx = ((((size_t)b_ * H + h_) * S + s_) << 6) + d_;
                    uint32_t hi, lo;
                    split_f16(vx, vy, hi, lo);
                    *(uint32_t*)(Chi + idx) = hi;
                    if (widx == 0) *(uint32_t*)(Qlo + idx) = lo;  // Q residual only
                }
            }
        }
    }
}

// ---------------------------------------------------------------------------
// Tensor-core causal flash attention, fp16 2-term (Q and P exact as hi+lo;
// K,V rounded once each -> ~2.8e-4/stage). 128 thr, 64 queries/CTA, KV tiles
// of 64, double-buffered cp.async; one barrier per tile; exp2-domain softmax.
// Writes AO as fp16 RN [b, s, h*64+d].
// ---------------------------------------------------------------------------
constexpr int AROWB = 144;
constexpr int ATILE = 64 * AROWB;       // 9216
constexpr int ASTG = 2 * ATILE;         // K, V
constexpr int ATT_SMEM = 2 * ASTG;      // 36864
constexpr float SC2 = 0.125f * 1.4426950408889634f;  // (1/sqrt(64)) * log2(e)

__global__ __launch_bounds__(128) void attn_mma(
    const __half* __restrict__ QKVh, const __half* __restrict__ Qlo,
    __half* __restrict__ AOh) {
    extern __shared__ char smem[];
    const uint32_t sb = smem_u32(smem);
    const int tid = threadIdx.x;
    const int lane = tid & 31;
    const int wid = tid >> 5;
    const int qt = blockIdx.x;
    const int h = blockIdx.y;
    const int b = blockIdx.z;
    const size_t hb = (((size_t)b * H + h) * S) * DH;
    const __half* Qh = QKVh;
    const __half* Kh = QKVh + (size_t)M * DM;
    const __half* Vh = QKVh + (size_t)2 * M * DM;

    // Stage Q hi/lo (64x64 each) into the two tiles of buffer 0
#pragma unroll
    for (int i = 0; i < 4; i++) {
        int id = tid + i * 128;
        int r = id >> 3, c = id & 7;
        uint32_t so = (uint32_t)(r * AROWB + c * 16);
        size_t g = hb + (size_t)(qt * 64 + r) * DH + c * 8;
        cp16(sb + so, Qh + g);
        cp16(sb + ATILE + so, Qlo + g);
    }
    cp_commit();
    cp_waitg<0>();
    __syncthreads();

    uint32_t qh[4][4], ql[4][4];
    {
        int row = wid * 16 + (lane & 15);
#pragma unroll
        for (int ks = 0; ks < 4; ks++) {
            uint32_t off = (uint32_t)(row * AROWB + (ks * 16 + (lane >> 4) * 8) * 2);
            ldsm4(qh[ks], sb + off);
            ldsm4(ql[ks], sb + ATILE + off);
        }
    }
    __syncthreads();

    float ov[8][4];
#pragma unroll
    for (int o = 0; o < 8; o++)
#pragma unroll
        for (int e = 0; e < 4; e++) ov[o][e] = 0.f;
    float m0 = -1e30f, m1 = -1e30f, l0 = 0.f, l1 = 0.f;

    const int nkt = qt + 1;

    auto load_kv = [&](int kt, int bufi) {
        uint32_t base = sb + bufi * ASTG;
#pragma unroll
        for (int i = 0; i < 4; i++) {
            int id = tid + i * 128;
            int r = id >> 3, c = id & 7;
            uint32_t so = (uint32_t)(r * AROWB + c * 16);
            size_t g = hb + (size_t)(kt * 64 + r) * DH + c * 8;
            cp16(base + so,         Kh + g);
            cp16(base + ATILE + so, Vh + g);
        }
        cp_commit();
    };
    load_kv(0, 0);

    const int q0 = qt * 64 + wid * 16 + (lane >> 2);
    const int q1 = q0 + 8;

    for (int kt = 0; kt < nkt; kt++) {
        const int buf = kt & 1;
        cp_waitg<0>();
        __syncthreads();   // tile(kt) visible AND compute(kt-1) done

        if (kt + 1 < nkt) load_kv(kt + 1, buf ^ 1);

        const uint32_t kb = sb + buf * ASTG;

        // S = (Qh + Ql) * K
        float sf[8][4];
#pragma unroll
        for (int o = 0; o < 8; o++)
#pragma unroll
            for (int e = 0; e < 4; e++) sf[o][e] = 0.f;

#pragma unroll
        for (int ks = 0; ks < 4; ks++) {
#pragma unroll
            for (int np = 0; np < 4; np++) {
                uint32_t kh4[4];
                uint32_t ro = (uint32_t)(
                    (np * 16 + (lane >> 4) * 8 + (lane & 7)) * AROWB +
                    (ks * 16 + ((lane >> 3) & 1) * 8) * 2);
                ldsm4(kh4, kb + ro);
#pragma unroll
                for (int ns = 0; ns < 2; ns++) {
                    float* c = sf[np * 2 + ns];
                    mma16816h(c, qh[ks], &kh4[ns * 2]);
                    mma16816h(c, ql[ks], &kh4[ns * 2]);
                }
            }
        }

        // online softmax in exp2 domain
        const bool diag = (kt == qt);
        float mx0 = -1e30f, mx1 = -1e30f;
#pragma unroll
        for (int o = 0; o < 8; o++) {
#pragma unroll
            for (int e = 0; e < 2; e++) {
                int keyl = o * 8 + (lane & 3) * 2 + e;
                float v0 = sf[o][e] * SC2;
                float v1 = sf[o][2 + e] * SC2;
                if (diag && keyl > q0 - qt * 64) v0 = -1e30f;
                if (diag && keyl > q1 - qt * 64) v1 = -1e30f;
                sf[o][e] = v0;
                sf[o][2 + e] = v1;
                mx0 = fmaxf(mx0, v0);
                mx1 = fmaxf(mx1, v1);
            }
        }
        mx0 = fmaxf(mx0, __shfl_xor_sync(0xffffffffu, mx0, 1));
        mx0 = fmaxf(mx0, __shfl_xor_sync(0xffffffffu, mx0, 2));
        mx1 = fmaxf(mx1, __shfl_xor_sync(0xffffffffu, mx1, 1));
        mx1 = fmaxf(mx1, __shfl_xor_sync(0xffffffffu, mx1, 2));
        const float mn0 = fmaxf(m0, mx0);
        const float mn1 = fmaxf(m1, mx1);
        const float es0 = exp2f(m0 - mn0);
        const float es1 = exp2f(m1 - mn1);
        m0 = mn0; m1 = mn1;

        float rs0 = 0.f, rs1 = 0.f;
#pragma unroll
        for (int o = 0; o < 8; o++) {
#pragma unroll
            for (int e = 0; e < 2; e++) {
                float p0 = exp2f(sf[o][e] - mn0);
                float p1 = exp2f(sf[o][2 + e] - mn1);
                sf[o][e] = p0;
                sf[o][2 + e] = p1;
                rs0 += p0;
                rs1 += p1;
            }
        }
        rs0 += __shfl_xor_sync(0xffffffffu, rs0, 1);
        rs0 += __shfl_xor_sync(0xffffffffu, rs0, 2);
        rs1 += __shfl_xor_sync(0xffffffffu, rs1, 1);
        rs1 += __shfl_xor_sync(0xffffffffu, rs1, 2);
        l0 = l0 * es0 + rs0;
        l1 = l1 * es1 + rs1;
#pragma unroll
        for (int o = 0; o < 8; o++) {
            ov[o][0] *= es0; ov[o][1] *= es0;
            ov[o][2] *= es1; ov[o][3] *= es1;
        }

        // O += (Ph + Pl) * V   (V via ldmatrix.trans)
#pragma unroll
        for (int kp = 0; kp < 4; kp++) {
            uint32_t pah[4], pal[4];
            split_f16(sf[2 * kp][0],     sf[2 * kp][1],     pah[0], pal[0]);
            split_f16(sf[2 * kp][2],     sf[2 * kp][3],     pah[1], pal[1]);
            split_f16(sf[2 * kp + 1][0], sf[2 * kp + 1][1], pah[2], pal[2]);
            split_f16(sf[2 * kp + 1][2], sf[2 * kp + 1][3], pah[3], pal[3]);
#pragma unroll
            for (int dp = 0; dp < 4; dp++) {
                uint32_t bvh[4];
                uint32_t vo = (uint32_t)(
                    (kp * 16 + (lane & 15)) * AROWB +
                    (dp * 16 + (lane >> 4) * 8) * 2);
                ldsm4t(bvh, kb + ATILE + vo);
#pragma unroll
                for (int ns = 0; ns < 2; ns++) {
                    float* o_ = ov[dp * 2 + ns];
                    mma16816h(o_, pah, &bvh[ns * 2]);
                    mma16816h(o_, pal, &bvh[ns * 2]);
                }
            }
        }
    }

    // epilogue: normalize, fp16 RN, write [b, s, h*64 + d]
    const float inv0 = 1.f / l0;
    const float inv1 = 1.f / l1;
    const int s0 = qt * 64 + wid * 16 + (lane >> 2);
    const size_t row0 = ((size_t)b * S + s0) * DM + h * DH;
    const size_t row1 = row0 + (size_t)8 * DM;
#pragma unroll
    for (int o = 0; o < 8; o++) {
        int d = o * 8 + (lane & 3) * 2;
        *(uint32_t*)(AOh + row0 + d) = pkh2(ov[o][0] * inv0, ov[o][1] * inv0);
        *(uint32_t*)(AOh + row1 + d) = pkh2(ov[o][2] * inv1, ov[o][3] * inv1);
    }
}

// ---------------------------------------------------------------------------
extern "C" void kernel_launch(void* const* d_in, const int* in_sizes, int n_in,
                              void* d_out, int out_size) {
    const float* w[4] = {nullptr, nullptr, nullptr, nullptr};
    const float* x = nullptr;
    int wn = 0;
    for (int i = 0; i < n_in; i++) {
        if (in_sizes[i] == DM * DM && wn < 4) {
            w[wn++] = (const float*)d_in[i];
        } else if (in_sizes[i] == B * S * DM) {
            x = (const float*)d_in[i];
        }
    }

    __half *xh, *whi, *qkvh, *qlo, *aoh;
    cudaGetSymbolAddress((void**)&xh, g_xh);
    cudaGetSymbolAddress((void**)&whi, g_whi);
    cudaGetSymbolAddress((void**)&qkvh, g_qkvh);
    cudaGetSymbolAddress((void**)&qlo, g_qlo);
    cudaGetSymbolAddress((void**)&aoh, g_aoh);

    cudaFuncSetAttribute(gemm_f16<0>, cudaFuncAttributeMaxDynamicSharedMemorySize, GEMM_SMEM);
    cudaFuncSetAttribute(gemm_f16<1>, cudaFuncAttributeMaxDynamicSharedMemorySize, GEMM_SMEM);
    cudaFuncSetAttribute(attn_mma, cudaFuncAttributeMaxDynamicSharedMemorySize, ATT_SMEM);

    split_all<<<(SPLIT_TOTAL + 255) / 256, 256>>>(
        (const float4*)x, (const float4*)w[0], (const float4*)w[1],
        (const float4*)w[2], (const float4*)w[3],
        (uint32_t*)xh, (uint32_t*)whi);

    dim3 qkvgrid(3 * DM / 128, M / 128);  // (24, 64)
    gemm_f16<1><<<qkvgrid, 256, GEMM_SMEM>>>(xh, whi, nullptr, qkvh, qlo);

    dim3 agrid(S / 64, H, B);  // (32, 16, 4)
    attn_mma<<<agrid, 128, ATT_SMEM>>>(qkvh, qlo, aoh);

    dim3 ogrid(DM / 128, M / 128);  // (8, 64)
    gemm_f16<0><<<ogrid, 256, GEMM_SMEM>>>(aoh, whi + (size_t)3 * DM * DM,
                                           (float*)d_out, nullptr, nullptr);
}

// round 11
// speedup vs baseline: 1.7261x; 1.0965x over previous
#include <cuda_runtime.h>
#include <cuda_bf16.h>
#include <cuda_fp16.h>
#include <cstdint>
#include <math.h>

// Problem constants
constexpr int DM = 1024;   // d_model
constexpr int H  = 16;     // heads
constexpr int DH = 64;     // head dim
constexpr int B  = 4;      // batch
constexpr int S  = 2048;   // seq len
constexpr int M  = B * S;  // 8192 rows

// Scratch (allocation-free rule: __device__ globals)
__device__ __half g_xh[(size_t)M * DM];                // x, fp16 RN
__device__ __half g_whi[(size_t)4 * DM * DM];          // weights, fp16 RN
__device__ __half g_qkvh[(size_t)3 * M * DM];          // q,k,v head-major fp16 hi
__device__ __half g_qlo[(size_t)M * DM];               // q lo residual (fp16)
__device__ __half g_aoh[(size_t)M * DM];               // attention out, fp16 RN

// ---------------------------------------------------------------------------
// PTX helpers (compute_103-safe)
// ---------------------------------------------------------------------------
__device__ __forceinline__ uint32_t smem_u32(const void* p) {
    uint32_t a;
    asm("{ .reg .u64 t; cvta.to.shared.u64 t, %1; cvt.u32.u64 %0, t; }"
        : "=r"(a) : "l"(p));
    return a;
}
__device__ __forceinline__ void cp16(uint32_t saddr, const void* gaddr) {
    asm volatile("cp.async.cg.shared.global [%0], [%1], 16;"
                 :: "r"(saddr), "l"(gaddr) : "memory");
}
__device__ __forceinline__ void cp_commit() {
    asm volatile("cp.async.commit_group;" ::: "memory");
}
template <int N>
__device__ __forceinline__ void cp_waitg() {
    asm volatile("cp.async.wait_group %0;" :: "n"(N) : "memory");
}
__device__ __forceinline__ void ldsm4(uint32_t* r, uint32_t addr) {
    asm volatile("ldmatrix.sync.aligned.m8n8.x4.shared.b16 {%0,%1,%2,%3}, [%4];"
                 : "=r"(r[0]), "=r"(r[1]), "=r"(r[2]), "=r"(r[3]) : "r"(addr));
}
__device__ __forceinline__ void ldsm4t(uint32_t* r, uint32_t addr) {
    asm volatile("ldmatrix.sync.aligned.m8n8.x4.trans.shared.b16 {%0,%1,%2,%3}, [%4];"
                 : "=r"(r[0]), "=r"(r[1]), "=r"(r[2]), "=r"(r[3]) : "r"(addr));
}
// fp16 mma
__device__ __forceinline__ void mma16816h(float* c, const uint32_t* a, const uint32_t* b) {
    asm volatile(
        "mma.sync.aligned.m16n8k16.row.col.f32.f16.f16.f32 "
        "{%0,%1,%2,%3}, {%4,%5,%6,%7}, {%8,%9}, {%0,%1,%2,%3};"
        : "+f"(c[0]), "+f"(c[1]), "+f"(c[2]), "+f"(c[3])
        : "r"(a[0]), "r"(a[1]), "r"(a[2]), "r"(a[3]), "r"(b[0]), "r"(b[1]));
}
// fp16 RN pack (a -> low half)
__device__ __forceinline__ uint32_t pkh2(float a, float b) {
    uint32_t r;
    asm("cvt.rn.f16x2.f32 %0, %1, %2;" : "=r"(r) : "f"(b), "f"(a));
    return r;
}
// fp16 hi/lo split of a float pair
__device__ __forceinline__ void split_f16(float a, float b, uint32_t& hi, uint32_t& lo) {
    __half ha = __float2half_rn(a);
    __half hb = __float2half_rn(b);
    hi = ((uint32_t)__half_as_ushort(hb) << 16) | __half_as_ushort(ha);
    lo = pkh2(a - __half2float(ha), b - __half2float(hb));
}

// ---------------------------------------------------------------------------
// Merged split: x -> fp16 RN, 4 weights -> fp16 RN. One launch.
// ---------------------------------------------------------------------------
constexpr int XN4 = (M * DM) / 4;     // 2M float4
constexpr int WN4 = (DM * DM) / 4;    // 256K float4
constexpr int SPLIT_TOTAL = XN4 + 4 * WN4;

__global__ __launch_bounds__(256) void split_all(
    const float4* __restrict__ x,
    const float4* __restrict__ w0, const float4* __restrict__ w1,
    const float4* __restrict__ w2, const float4* __restrict__ w3,
    uint32_t* __restrict__ xh, uint32_t* __restrict__ whi) {
    int i = blockIdx.x * 256 + threadIdx.x;
    if (i >= SPLIT_TOTAL) return;
    if (i < XN4) {
        float4 v = x[i];
        xh[2 * i]     = pkh2(v.x, v.y);
        xh[2 * i + 1] = pkh2(v.z, v.w);
    } else {
        int j = i - XN4;
        int widx = j >> 18;            // / WN4
        int wj = j & (WN4 - 1);
        const float4* ws[4] = {w0, w1, w2, w3};
        float4 v = ws[widx][wj];
        size_t o = (size_t)widx * (2 * WN4) + 2 * wj;
        whi[o]     = pkh2(v.x, v.y);
        whi[o + 1] = pkh2(v.z, v.w);
    }
}

// ---------------------------------------------------------------------------
// fp16 single-term GEMM: C[M,N] = Ah[M,K] @ Wh[N,K]^T, fp32 accumulate.
// BM=128 BN=128 BK=32, 256 thr: 8 warps 4x2 -> warp tile 32x64.
// 4-stage cp.async pipeline, one barrier per k-iter.
// OUTBF=1: fused QKV (grid.x=24, widx=bn>>3), fp16 head-major out
//          (hi for q/k/v; lo residual only for q, widx==0).
// ---------------------------------------------------------------------------
constexpr int ROWB = 80;
constexpr int TILEB = 128 * ROWB;            // 10240
constexpr int NSTG = 4;
constexpr int A_REG = NSTG * TILEB;          // 40960
constexpr int GEMM_SMEM = 2 * A_REG;         // 81920
constexpr int NKT = DM / 32;

template <int OUTBF>
__global__ __launch_bounds__(256) void gemm_f16(const __half* __restrict__ Ah,
                                                const __half* __restrict__ Wh,
                                                float* __restrict__ C,
                                                __half* __restrict__ QKVh,
                                                __half* __restrict__ Qlo) {
    extern __shared__ char smem[];
    const uint32_t sb = smem_u32(smem);
    const int tid = threadIdx.x;
    const int lane = tid & 31;
    const int wid = tid >> 5;
    const int warpM = wid & 3;
    const int warpN = wid >> 2;
    const int bn = blockIdx.x;
    const int bm = blockIdx.y;
    const int widx = (OUTBF == 1) ? (bn >> 3) : 0;
    const int bnl = (OUTBF == 1) ? (bn & 7) : bn;
    const int rowA0 = bm * 128;
    const int rowB0 = bnl * 128;
    const __half* Bh = Wh + (size_t)widx * DM * DM;

    const int lr0 = tid >> 2;
    const int lc = (tid & 3) * 8;

    auto load_stage = [&](int kt, int buf) {
        const size_t gkoff = (size_t)kt * 32 + lc;
#pragma unroll
        for (int it = 0; it < 2; it++) {
            int r = lr0 + it * 64;
            uint32_t so = (uint32_t)(r * ROWB + (tid & 3) * 16);
            size_t ga = (size_t)(rowA0 + r) * DM + gkoff;
            size_t gb = (size_t)(rowB0 + r) * DM + gkoff;
            cp16(sb + buf * TILEB + so,         Ah + ga);
            cp16(sb + A_REG + buf * TILEB + so, Bh + gb);
        }
        cp_commit();
    };

    float acc[2][8][4];
#pragma unroll
    for (int i = 0; i < 2; i++)
#pragma unroll
        for (int j = 0; j < 8; j++)
#pragma unroll
            for (int e = 0; e < 4; e++) acc[i][j][e] = 0.f;

    load_stage(0, 0);
    load_stage(1, 1);
    load_stage(2, 2);

    const int a_r = (lane & 15);
    const int a_c8 = (lane >> 4) * 8;
    const int b_r = ((lane >> 4) * 8) + (lane & 7);
    const int b_c8 = ((lane >> 3) & 1) * 8;

    for (int kt = 0; kt < NKT; kt++) {
        const int buf = kt & 3;
        cp_waitg<2>();
        __syncthreads();

        int ktn = kt + 3;
        if (ktn > NKT - 1) ktn = NKT - 1;
        load_stage(ktn, (kt + 3) & 3);

        const uint32_t aHi = sb + buf * TILEB;
        const uint32_t bHi = sb + A_REG + buf * TILEB;
        const int mrow = warpM * 32 + a_r;
        const int nrow0 = warpN * 64 + b_r;

#pragma unroll
        for (int ks = 0; ks < 2; ks++) {
            uint32_t ah[2][4], bh[4][4];
            const uint32_t acol = (uint32_t)((ks * 16 + a_c8) * 2);
            const uint32_t bcol = (uint32_t)((ks * 16 + b_c8) * 2);
#pragma unroll
            for (int mt = 0; mt < 2; mt++) {
                uint32_t ro = (uint32_t)((mrow + mt * 16) * ROWB) + acol;
                ldsm4(ah[mt], aHi + ro);
            }
#pragma unroll
            for (int np = 0; np < 4; np++) {
                uint32_t ro = (uint32_t)((nrow0 + np * 16) * ROWB) + bcol;
                ldsm4(bh[np], bHi + ro);
            }
#pragma unroll
            for (int mt = 0; mt < 2; mt++)
#pragma unroll
                for (int np = 0; np < 4; np++)
#pragma unroll
                    for (int ns = 0; ns < 2; ns++)
                        mma16816h(acc[mt][np * 2 + ns], ah[mt], &bh[np][ns * 2]);
        }
    }

    const int rbase = bm * 128 + warpM * 32 + (lane >> 2);
    const int cbase = bnl * 128 + warpN * 64 + (lane & 3) * 2;
    __half* Chi = QKVh + (size_t)widx * M * DM;
#pragma unroll
    for (int mt = 0; mt < 2; mt++) {
#pragma unroll
        for (int nt = 0; nt < 8; nt++) {
            int row = rbase + mt * 16;
            int col = cbase + nt * 8;
#pragma unroll
            for (int half = 0; half < 2; half++) {
                int r = row + half * 8;
                float vx = acc[mt][nt][half * 2];
                float vy = acc[mt][nt][half * 2 + 1];
                if (OUTBF == 0) {
                    *(float2*)(C + (size_t)r * DM + col) = make_float2(vx, vy);
                } else {
                    int b_ = r >> 11;
                    int s_ = r & 2047;
                    int h_ = col >> 6;
                    int d_ = col & 63;
                    size_t idx = ((((size_t)b_ * H + h_) * S + s_) << 6) + d_;
                    uint32_t hi, lo;
                    split_f16(vx, vy, hi, lo);
                    *(uint32_t*)(Chi + idx) = hi;
                    if (widx == 0) *(uint32_t*)(Qlo + idx) = lo;  // Q residual only
                }
            }
        }
    }
}

// ---------------------------------------------------------------------------
// Tensor-core causal flash attention: S = (Qh+Ql)*K (2-term), O = P*V
// (1-term, P fp16 RN). 128 thr, 64 queries/CTA, KV tiles of 64,
// double-buffered cp.async; one barrier per tile; exp2-domain softmax.
// Longest CTAs launched first (qt reversed). AO out fp16 RN [b,s,h*64+d].
// ---------------------------------------------------------------------------
constexpr int AROWB = 144;
constexpr int ATILE = 64 * AROWB;       // 9216
constexpr int ASTG = 2 * ATILE;         // K, V
constexpr int ATT_SMEM = 2 * ASTG;      // 36864
constexpr float SC2 = 0.125f * 1.4426950408889634f;  // (1/sqrt(64)) * log2(e)

__global__ __launch_bounds__(128) void attn_mma(
    const __half* __restrict__ QKVh, const __half* __restrict__ Qlo,
    __half* __restrict__ AOh) {
    extern __shared__ char smem[];
    const uint32_t sb = smem_u32(smem);
    const int tid = threadIdx.x;
    const int lane = tid & 31;
    const int wid = tid >> 5;
    const int qt = (int)gridDim.x - 1 - (int)blockIdx.x;  // longest first
    const int h = blockIdx.y;
    const int b = blockIdx.z;
    const size_t hb = (((size_t)b * H + h) * S) * DH;
    const __half* Qh = QKVh;
    const __half* Kh = QKVh + (size_t)M * DM;
    const __half* Vh = QKVh + (size_t)2 * M * DM;

    // Stage Q hi/lo (64x64 each) into the two tiles of buffer 0
#pragma unroll
    for (int i = 0; i < 4; i++) {
        int id = tid + i * 128;
        int r = id >> 3, c = id & 7;
        uint32_t so = (uint32_t)(r * AROWB + c * 16);
        size_t g = hb + (size_t)(qt * 64 + r) * DH + c * 8;
        cp16(sb + so, Qh + g);
        cp16(sb + ATILE + so, Qlo + g);
    }
    cp_commit();
    cp_waitg<0>();
    __syncthreads();

    uint32_t qh[4][4], ql[4][4];
    {
        int row = wid * 16 + (lane & 15);
#pragma unroll
        for (int ks = 0; ks < 4; ks++) {
            uint32_t off = (uint32_t)(row * AROWB + (ks * 16 + (lane >> 4) * 8) * 2);
            ldsm4(qh[ks], sb + off);
            ldsm4(ql[ks], sb + ATILE + off);
        }
    }
    __syncthreads();

    float ov[8][4];
#pragma unroll
    for (int o = 0; o < 8; o++)
#pragma unroll
        for (int e = 0; e < 4; e++) ov[o][e] = 0.f;
    float m0 = -1e30f, m1 = -1e30f, l0 = 0.f, l1 = 0.f;

    const int nkt = qt + 1;

    auto load_kv = [&](int kt, int bufi) {
        uint32_t base = sb + bufi * ASTG;
#pragma unroll
        for (int i = 0; i < 4; i++) {
            int id = tid + i * 128;
            int r = id >> 3, c = id & 7;
            uint32_t so = (uint32_t)(r * AROWB + c * 16);
            size_t g = hb + (size_t)(kt * 64 + r) * DH + c * 8;
            cp16(base + so,         Kh + g);
            cp16(base + ATILE + so, Vh + g);
        }
        cp_commit();
    };
    load_kv(0, 0);

    const int q0 = qt * 64 + wid * 16 + (lane >> 2);
    const int q1 = q0 + 8;

    for (int kt = 0; kt < nkt; kt++) {
        const int buf = kt & 1;
        cp_waitg<0>();
        __syncthreads();   // tile(kt) visible AND compute(kt-1) done

        if (kt + 1 < nkt) load_kv(kt + 1, buf ^ 1);

        const uint32_t kb = sb + buf * ASTG;

        // S = (Qh + Ql) * K
        float sf[8][4];
#pragma unroll
        for (int o = 0; o < 8; o++)
#pragma unroll
            for (int e = 0; e < 4; e++) sf[o][e] = 0.f;

#pragma unroll
        for (int ks = 0; ks < 4; ks++) {
#pragma unroll
            for (int np = 0; np < 4; np++) {
                uint32_t kh4[4];
                uint32_t ro = (uint32_t)(
                    (np * 16 + (lane >> 4) * 8 + (lane & 7)) * AROWB +
                    (ks * 16 + ((lane >> 3) & 1) * 8) * 2);
                ldsm4(kh4, kb + ro);
#pragma unroll
                for (int ns = 0; ns < 2; ns++) {
                    float* c = sf[np * 2 + ns];
                    mma16816h(c, qh[ks], &kh4[ns * 2]);
                    mma16816h(c, ql[ks], &kh4[ns * 2]);
                }
            }
        }

        // online softmax in exp2 domain
        const bool diag = (kt == qt);
        float mx0 = -1e30f, mx1 = -1e30f;
#pragma unroll
        for (int o = 0; o < 8; o++) {
#pragma unroll
            for (int e = 0; e < 2; e++) {
                int keyl = o * 8 + (lane & 3) * 2 + e;
                float v0 = sf[o][e] * SC2;
                float v1 = sf[o][2 + e] * SC2;
                if (diag && keyl > q0 - qt * 64) v0 = -1e30f;
                if (diag && keyl > q1 - qt * 64) v1 = -1e30f;
                sf[o][e] = v0;
                sf[o][2 + e] = v1;
                mx0 = fmaxf(mx0, v0);
                mx1 = fmaxf(mx1, v1);
            }
        }
        mx0 = fmaxf(mx0, __shfl_xor_sync(0xffffffffu, mx0, 1));
        mx0 = fmaxf(mx0, __shfl_xor_sync(0xffffffffu, mx0, 2));
        mx1 = fmaxf(mx1, __shfl_xor_sync(0xffffffffu, mx1, 1));
        mx1 = fmaxf(mx1, __shfl_xor_sync(0xffffffffu, mx1, 2));
        const float mn0 = fmaxf(m0, mx0);
        const float mn1 = fmaxf(m1, mx1);
        const float es0 = exp2f(m0 - mn0);
        const float es1 = exp2f(m1 - mn1);
        m0 = mn0; m1 = mn1;

        float rs0 = 0.f, rs1 = 0.f;
#pragma unroll
        for (int o = 0; o < 8; o++) {
#pragma unroll
            for (int e = 0; e < 2; e++) {
                float p0 = exp2f(sf[o][e] - mn0);
                float p1 = exp2f(sf[o][2 + e] - mn1);
                sf[o][e] = p0;
                sf[o][2 + e] = p1;
                rs0 += p0;
                rs1 += p1;
            }
        }
        rs0 += __shfl_xor_sync(0xffffffffu, rs0, 1);
        rs0 += __shfl_xor_sync(0xffffffffu, rs0, 2);
        rs1 += __shfl_xor_sync(0xffffffffu, rs1, 1);
        rs1 += __shfl_xor_sync(0xffffffffu, rs1, 2);
        l0 = l0 * es0 + rs0;
        l1 = l1 * es1 + rs1;
#pragma unroll
        for (int o = 0; o < 8; o++) {
            ov[o][0] *= es0; ov[o][1] *= es0;
            ov[o][2] *= es1; ov[o][3] *= es1;
        }

        // O += P * V   (single term, P fp16 RN; V via ldmatrix.trans)
#pragma unroll
        for (int kp = 0; kp < 4; kp++) {
            uint32_t pah[4];
            pah[0] = pkh2(sf[2 * kp][0],     sf[2 * kp][1]);
            pah[1] = pkh2(sf[2 * kp][2],     sf[2 * kp][3]);
            pah[2] = pkh2(sf[2 * kp + 1][0], sf[2 * kp + 1][1]);
            pah[3] = pkh2(sf[2 * kp + 1][2], sf[2 * kp + 1][3]);
#pragma unroll
            for (int dp = 0; dp < 4; dp++) {
                uint32_t bvh[4];
                uint32_t vo = (uint32_t)(
                    (kp * 16 + (lane & 15)) * AROWB +
                    (dp * 16 + (lane >> 4) * 8) * 2);
                ldsm4t(bvh, kb + ATILE + vo);
#pragma unroll
                for (int ns = 0; ns < 2; ns++)
                    mma16816h(ov[dp * 2 + ns], pah, &bvh[ns * 2]);
            }
        }
    }

    // epilogue: normalize, fp16 RN, write [b, s, h*64 + d]
    const float inv0 = 1.f / l0;
    const float inv1 = 1.f / l1;
    const int s0 = qt * 64 + wid * 16 + (lane >> 2);
    const size_t row0 = ((size_t)b * S + s0) * DM + h * DH;
    const size_t row1 = row0 + (size_t)8 * DM;
#pragma unroll
    for (int o = 0; o < 8; o++) {
        int d = o * 8 + (lane & 3) * 2;
        *(uint32_t*)(AOh + row0 + d) = pkh2(ov[o][0] * inv0, ov[o][1] * inv0);
        *(uint32_t*)(AOh + row1 + d) = pkh2(ov[o][2] * inv1, ov[o][3] * inv1);
    }
}

// ---------------------------------------------------------------------------
extern "C" void kernel_launch(void* const* d_in, const int* in_sizes, int n_in,
                              void* d_out, int out_size) {
    const float* w[4] = {nullptr, nullptr, nullptr, nullptr};
    const float* x = nullptr;
    int wn = 0;
    for (int i = 0; i < n_in; i++) {
        if (in_sizes[i] == DM * DM && wn < 4) {
            w[wn++] = (const float*)d_in[i];
        } else if (in_sizes[i] == B * S * DM) {
            x = (const float*)d_in[i];
        }
    }

    __half *xh, *whi, *qkvh, *qlo, *aoh;
    cudaGetSymbolAddress((void**)&xh, g_xh);
    cudaGetSymbolAddress((void**)&whi, g_whi);
    cudaGetSymbolAddress((void**)&qkvh, g_qkvh);
    cudaGetSymbolAddress((void**)&qlo, g_qlo);
    cudaGetSymbolAddress((void**)&aoh, g_aoh);

    cudaFuncSetAttribute(gemm_f16<0>, cudaFuncAttributeMaxDynamicSharedMemorySize, GEMM_SMEM);
    cudaFuncSetAttribute(gemm_f16<1>, cudaFuncAttributeMaxDynamicSharedMemorySize, GEMM_SMEM);
    cudaFuncSetAttribute(attn_mma, cudaFuncAttributeMaxDynamicSharedMemorySize, ATT_SMEM);

    split_all<<<(SPLIT_TOTAL + 255) / 256, 256>>>(
        (const float4*)x, (const float4*)w[0], (const float4*)w[1],
        (const float4*)w[2], (const float4*)w[3],
        (uint32_t*)xh, (uint32_t*)whi);

    dim3 qkvgrid(3 * DM / 128, M / 128);  // (24, 64)
    gemm_f16<1><<<qkvgrid, 256, GEMM_SMEM>>>(xh, whi, nullptr, qkvh, qlo);

    dim3 agrid(S / 64, H, B);  // (32, 16, 4)
    attn_mma<<<agrid, 128, ATT_SMEM>>>(qkvh, qlo, aoh);

    dim3 ogrid(DM / 128, M / 128);  // (8, 64)
    gemm_f16<0><<<ogrid, 256, GEMM_SMEM>>>(aoh, whi + (size_t)3 * DM * DM,
                                           (float*)d_out, nullptr, nullptr);
}

// round 12
// speedup vs baseline: 2.1184x; 1.2273x over previous
#include <cuda_runtime.h>
#include <cuda_bf16.h>
#include <cuda_fp16.h>
#include <cstdint>
#include <math.h>

// Problem constants
constexpr int DM = 1024;   // d_model
constexpr int H  = 16;     // heads
constexpr int DH = 64;     // head dim
constexpr int B  = 4;      // batch
constexpr int S  = 2048;   // seq len
constexpr int M  = B * S;  // 8192 rows

// Scratch (allocation-free rule: __device__ globals)
__device__ __half g_xh[(size_t)M * DM];                // x, fp16 RN
__device__ __half g_whi[(size_t)4 * DM * DM];          // weights, fp16 RN
__device__ __half g_qkvh[(size_t)3 * M * DM];          // q,k,v head-major fp16
__device__ __half g_aoh[(size_t)M * DM];               // attention out, fp16 RN

// ---------------------------------------------------------------------------
// PTX helpers (compute_103-safe)
// ---------------------------------------------------------------------------
__device__ __forceinline__ uint32_t smem_u32(const void* p) {
    uint32_t a;
    asm("{ .reg .u64 t; cvta.to.shared.u64 t, %1; cvt.u32.u64 %0, t; }"
        : "=r"(a) : "l"(p));
    return a;
}
__device__ __forceinline__ void cp16(uint32_t saddr, const void* gaddr) {
    asm volatile("cp.async.cg.shared.global [%0], [%1], 16;"
                 :: "r"(saddr), "l"(gaddr) : "memory");
}
__device__ __forceinline__ void cp_commit() {
    asm volatile("cp.async.commit_group;" ::: "memory");
}
template <int N>
__device__ __forceinline__ void cp_waitg() {
    asm volatile("cp.async.wait_group %0;" :: "n"(N) : "memory");
}
__device__ __forceinline__ void ldsm4(uint32_t* r, uint32_t addr) {
    asm volatile("ldmatrix.sync.aligned.m8n8.x4.shared.b16 {%0,%1,%2,%3}, [%4];"
                 : "=r"(r[0]), "=r"(r[1]), "=r"(r[2]), "=r"(r[3]) : "r"(addr));
}
__device__ __forceinline__ void ldsm4t(uint32_t* r, uint32_t addr) {
    asm volatile("ldmatrix.sync.aligned.m8n8.x4.trans.shared.b16 {%0,%1,%2,%3}, [%4];"
                 : "=r"(r[0]), "=r"(r[1]), "=r"(r[2]), "=r"(r[3]) : "r"(addr));
}
// fp16 mma
__device__ __forceinline__ void mma16816h(float* c, const uint32_t* a, const uint32_t* b) {
    asm volatile(
        "mma.sync.aligned.m16n8k16.row.col.f32.f16.f16.f32 "
        "{%0,%1,%2,%3}, {%4,%5,%6,%7}, {%8,%9}, {%0,%1,%2,%3};"
        : "+f"(c[0]), "+f"(c[1]), "+f"(c[2]), "+f"(c[3])
        : "r"(a[0]), "r"(a[1]), "r"(a[2]), "r"(a[3]), "r"(b[0]), "r"(b[1]));
}
// fp16 RN pack (a -> low half)
__device__ __forceinline__ uint32_t pkh2(float a, float b) {
    uint32_t r;
    asm("cvt.rn.f16x2.f32 %0, %1, %2;" : "=r"(r) : "f"(b), "f"(a));
    return r;
}

// ---------------------------------------------------------------------------
// Merged split: x -> fp16 RN, 4 weights -> fp16 RN. One launch.
// ---------------------------------------------------------------------------
constexpr int XN4 = (M * DM) / 4;     // 2M float4
constexpr int WN4 = (DM * DM) / 4;    // 256K float4
constexpr int SPLIT_TOTAL = XN4 + 4 * WN4;

__global__ __launch_bounds__(256) void split_all(
    const float4* __restrict__ x,
    const float4* __restrict__ w0, const float4* __restrict__ w1,
    const float4* __restrict__ w2, const float4* __restrict__ w3,
    uint32_t* __restrict__ xh, uint32_t* __restrict__ whi) {
    int i = blockIdx.x * 256 + threadIdx.x;
    if (i >= SPLIT_TOTAL) return;
    if (i < XN4) {
        float4 v = x[i];
        xh[2 * i]     = pkh2(v.x, v.y);
        xh[2 * i + 1] = pkh2(v.z, v.w);
    } else {
        int j = i - XN4;
        int widx = j >> 18;            // / WN4
        int wj = j & (WN4 - 1);
        const float4* ws[4] = {w0, w1, w2, w3};
        float4 v = ws[widx][wj];
        size_t o = (size_t)widx * (2 * WN4) + 2 * wj;
        whi[o]     = pkh2(v.x, v.y);
        whi[o + 1] = pkh2(v.z, v.w);
    }
}

// ---------------------------------------------------------------------------
// fp16 single-term GEMM: C[M,N] = Ah[M,K] @ Wh[N,K]^T, fp32 accumulate.
// BM=128 BN=128 BK=32, 256 thr: 8 warps 4x2 -> warp tile 32x64.
// 4-stage cp.async pipeline, one barrier per k-iter.
// OUTBF=1: fused QKV (grid.x=24, widx=bn>>3), fp16 RN head-major out.
// ---------------------------------------------------------------------------
constexpr int ROWB = 80;
constexpr int TILEB = 128 * ROWB;            // 10240
constexpr int NSTG = 4;
constexpr int A_REG = NSTG * TILEB;          // 40960
constexpr int GEMM_SMEM = 2 * A_REG;         // 81920
constexpr int NKT = DM / 32;

template <int OUTBF>
__global__ __launch_bounds__(256) void gemm_f16(const __half* __restrict__ Ah,
                                                const __half* __restrict__ Wh,
                                                float* __restrict__ C,
                                                __half* __restrict__ QKVh) {
    extern __shared__ char smem[];
    const uint32_t sb = smem_u32(smem);
    const int tid = threadIdx.x;
    const int lane = tid & 31;
    const int wid = tid >> 5;
    const int warpM = wid & 3;
    const int warpN = wid >> 2;
    const int bn = blockIdx.x;
    const int bm = blockIdx.y;
    const int widx = (OUTBF == 1) ? (bn >> 3) : 0;
    const int bnl = (OUTBF == 1) ? (bn & 7) : bn;
    const int rowA0 = bm * 128;
    const int rowB0 = bnl * 128;
    const __half* Bh = Wh + (size_t)widx * DM * DM;

    const int lr0 = tid >> 2;
    const int lc = (tid & 3) * 8;

    auto load_stage = [&](int kt, int buf) {
        const size_t gkoff = (size_t)kt * 32 + lc;
#pragma unroll
        for (int it = 0; it < 2; it++) {
            int r = lr0 + it * 64;
            uint32_t so = (uint32_t)(r * ROWB + (tid & 3) * 16);
            size_t ga = (size_t)(rowA0 + r) * DM + gkoff;
            size_t gb = (size_t)(rowB0 + r) * DM + gkoff;
            cp16(sb + buf * TILEB + so,         Ah + ga);
            cp16(sb + A_REG + buf * TILEB + so, Bh + gb);
        }
        cp_commit();
    };

    float acc[2][8][4];
#pragma unroll
    for (int i = 0; i < 2; i++)
#pragma unroll
        for (int j = 0; j < 8; j++)
#pragma unroll
            for (int e = 0; e < 4; e++) acc[i][j][e] = 0.f;

    load_stage(0, 0);
    load_stage(1, 1);
    load_stage(2, 2);

    const int a_r = (lane & 15);
    const int a_c8 = (lane >> 4) * 8;
    const int b_r = ((lane >> 4) * 8) + (lane & 7);
    const int b_c8 = ((lane >> 3) & 1) * 8;

    for (int kt = 0; kt < NKT; kt++) {
        const int buf = kt & 3;
        cp_waitg<2>();
        __syncthreads();

        int ktn = kt + 3;
        if (ktn > NKT - 1) ktn = NKT - 1;
        load_stage(ktn, (kt + 3) & 3);

        const uint32_t aHi = sb + buf * TILEB;
        const uint32_t bHi = sb + A_REG + buf * TILEB;
        const int mrow = warpM * 32 + a_r;
        const int nrow0 = warpN * 64 + b_r;

#pragma unroll
        for (int ks = 0; ks < 2; ks++) {
            uint32_t ah[2][4], bh[4][4];
            const uint32_t acol = (uint32_t)((ks * 16 + a_c8) * 2);
            const uint32_t bcol = (uint32_t)((ks * 16 + b_c8) * 2);
#pragma unroll
            for (int mt = 0; mt < 2; mt++) {
                uint32_t ro = (uint32_t)((mrow + mt * 16) * ROWB) + acol;
                ldsm4(ah[mt], aHi + ro);
            }
#pragma unroll
            for (int np = 0; np < 4; np++) {
                uint32_t ro = (uint32_t)((nrow0 + np * 16) * ROWB) + bcol;
                ldsm4(bh[np], bHi + ro);
            }
#pragma unroll
            for (int mt = 0; mt < 2; mt++)
#pragma unroll
                for (int np = 0; np < 4; np++)
#pragma unroll
                    for (int ns = 0; ns < 2; ns++)
                        mma16816h(acc[mt][np * 2 + ns], ah[mt], &bh[np][ns * 2]);
        }
    }

    const int rbase = bm * 128 + warpM * 32 + (lane >> 2);
    const int cbase = bnl * 128 + warpN * 64 + (lane & 3) * 2;
    __half* Chi = QKVh + (size_t)widx * M * DM;
#pragma unroll
    for (int mt = 0; mt < 2; mt++) {
#pragma unroll
        for (int nt = 0; nt < 8; nt++) {
            int row = rbase + mt * 16;
            int col = cbase + nt * 8;
#pragma unroll
            for (int half = 0; half < 2; half++) {
                int r = row + half * 8;
                float vx = acc[mt][nt][half * 2];
                float vy = acc[mt][nt][half * 2 + 1];
                if (OUTBF == 0) {
                    *(float2*)(C + (size_t)r * DM + col) = make_float2(vx, vy);
                } else {
                    int b_ = r >> 11;
                    int s_ = r & 2047;
                    int h_ = col >> 6;
                    int d_ = col & 63;
                    size_t idx = ((((size_t)b_ * H + h_) * S + s_) << 6) + d_;
                    *(uint32_t*)(Chi + idx) = pkh2(vx, vy);
                }
            }
        }
    }
}

// ---------------------------------------------------------------------------
// Tensor-core causal flash attention, fully fp16 single-term
// (Q, K, V, P all fp16 RN; fp32 accumulate + fp32 softmax).
// 128 thr, 64 queries/CTA, KV tiles of 64, double-buffered cp.async;
// one barrier per tile; exp2-domain softmax; longest CTAs first.
// AO out fp16 RN [b, s, h*64+d].
// ---------------------------------------------------------------------------
constexpr int AROWB = 144;
constexpr int ATILE = 64 * AROWB;       // 9216
constexpr int ASTG = 2 * ATILE;         // K, V
constexpr int ATT_SMEM = 2 * ASTG;      // 36864
constexpr float SC2 = 0.125f * 1.4426950408889634f;  // (1/sqrt(64)) * log2(e)

__global__ __launch_bounds__(128) void attn_mma(
    const __half* __restrict__ QKVh, __half* __restrict__ AOh) {
    extern __shared__ char smem[];
    const uint32_t sb = smem_u32(smem);
    const int tid = threadIdx.x;
    const int lane = tid & 31;
    const int wid = tid >> 5;
    const int qt = (int)gridDim.x - 1 - (int)blockIdx.x;  // longest first
    const int h = blockIdx.y;
    const int b = blockIdx.z;
    const size_t hb = (((size_t)b * H + h) * S) * DH;
    const __half* Qh = QKVh;
    const __half* Kh = QKVh + (size_t)M * DM;
    const __half* Vh = QKVh + (size_t)2 * M * DM;

    // Stage Q (64x64) into buffer 0's first tile, extract to regs
#pragma unroll
    for (int i = 0; i < 4; i++) {
        int id = tid + i * 128;
        int r = id >> 3, c = id & 7;
        if (i < 2 || id < 512) {
            uint32_t so = (uint32_t)(r * AROWB + c * 16);
            size_t g = hb + (size_t)(qt * 64 + r) * DH + c * 8;
            if (id < 512) cp16(sb + so, Qh + g);
        }
    }
    cp_commit();
    cp_waitg<0>();
    __syncthreads();

    uint32_t qh[4][4];
    {
        int row = wid * 16 + (lane & 15);
#pragma unroll
        for (int ks = 0; ks < 4; ks++) {
            uint32_t off = (uint32_t)(row * AROWB + (ks * 16 + (lane >> 4) * 8) * 2);
            ldsm4(qh[ks], sb + off);
        }
    }
    __syncthreads();

    float ov[8][4];
#pragma unroll
    for (int o = 0; o < 8; o++)
#pragma unroll
        for (int e = 0; e < 4; e++) ov[o][e] = 0.f;
    float m0 = -1e30f, m1 = -1e30f, l0 = 0.f, l1 = 0.f;

    const int nkt = qt + 1;

    auto load_kv = [&](int kt, int bufi) {
        uint32_t base = sb + bufi * ASTG;
#pragma unroll
        for (int i = 0; i < 4; i++) {
            int id = tid + i * 128;
            int r = id >> 3, c = id & 7;
            uint32_t so = (uint32_t)(r * AROWB + c * 16);
            size_t g = hb + (size_t)(kt * 64 + r) * DH + c * 8;
            cp16(base + so,         Kh + g);
            cp16(base + ATILE + so, Vh + g);
        }
        cp_commit();
    };
    load_kv(0, 0);

    const int q0 = qt * 64 + wid * 16 + (lane >> 2);
    const int q1 = q0 + 8;

    for (int kt = 0; kt < nkt; kt++) {
        const int buf = kt & 1;
        cp_waitg<0>();
        __syncthreads();   // tile(kt) visible AND compute(kt-1) done

        if (kt + 1 < nkt) load_kv(kt + 1, buf ^ 1);

        const uint32_t kb = sb + buf * ASTG;

        // S = Q * K
        float sf[8][4];
#pragma unroll
        for (int o = 0; o < 8; o++)
#pragma unroll
            for (int e = 0; e < 4; e++) sf[o][e] = 0.f;

#pragma unroll
        for (int ks = 0; ks < 4; ks++) {
#pragma unroll
            for (int np = 0; np < 4; np++) {
                uint32_t kh4[4];
                uint32_t ro = (uint32_t)(
                    (np * 16 + (lane >> 4) * 8 + (lane & 7)) * AROWB +
                    (ks * 16 + ((lane >> 3) & 1) * 8) * 2);
                ldsm4(kh4, kb + ro);
#pragma unroll
                for (int ns = 0; ns < 2; ns++)
                    mma16816h(sf[np * 2 + ns], qh[ks], &kh4[ns * 2]);
            }
        }

        // online softmax in exp2 domain
        const bool diag = (kt == qt);
        float mx0 = -1e30f, mx1 = -1e30f;
#pragma unroll
        for (int o = 0; o < 8; o++) {
#pragma unroll
            for (int e = 0; e < 2; e++) {
                int keyl = o * 8 + (lane & 3) * 2 + e;
                float v0 = sf[o][e] * SC2;
                float v1 = sf[o][2 + e] * SC2;
                if (diag && keyl > q0 - qt * 64) v0 = -1e30f;
                if (diag && keyl > q1 - qt * 64) v1 = -1e30f;
                sf[o][e] = v0;
                sf[o][2 + e] = v1;
                mx0 = fmaxf(mx0, v0);
                mx1 = fmaxf(mx1, v1);
            }
        }
        mx0 = fmaxf(mx0, __shfl_xor_sync(0xffffffffu, mx0, 1));
        mx0 = fmaxf(mx0, __shfl_xor_sync(0xffffffffu, mx0, 2));
        mx1 = fmaxf(mx1, __shfl_xor_sync(0xffffffffu, mx1, 1));
        mx1 = fmaxf(mx1, __shfl_xor_sync(0xffffffffu, mx1, 2));
        const float mn0 = fmaxf(m0, mx0);
        const float mn1 = fmaxf(m1, mx1);
        const float es0 = exp2f(m0 - mn0);
        const float es1 = exp2f(m1 - mn1);
        m0 = mn0; m1 = mn1;

        float rs0 = 0.f, rs1 = 0.f;
#pragma unroll
        for (int o = 0; o < 8; o++) {
#pragma unroll
            for (int e = 0; e < 2; e++) {
                float p0 = exp2f(sf[o][e] - mn0);
                float p1 = exp2f(sf[o][2 + e] - mn1);
                sf[o][e] = p0;
                sf[o][2 + e] = p1;
                rs0 += p0;
                rs1 += p1;
            }
        }
        rs0 += __shfl_xor_sync(0xffffffffu, rs0, 1);
        rs0 += __shfl_xor_sync(0xffffffffu, rs0, 2);
        rs1 += __shfl_xor_sync(0xffffffffu, rs1, 1);
        rs1 += __shfl_xor_sync(0xffffffffu, rs1, 2);
        l0 = l0 * es0 + rs0;
        l1 = l1 * es1 + rs1;
#pragma unroll
        for (int o = 0; o < 8; o++) {
            ov[o][0] *= es0; ov[o][1] *= es0;
            ov[o][2] *= es1; ov[o][3] *= es1;
        }

        // O += P * V   (P fp16 RN; V via ldmatrix.trans)
#pragma unroll
        for (int kp = 0; kp < 4; kp++) {
            uint32_t pah[4];
            pah[0] = pkh2(sf[2 * kp][0],     sf[2 * kp][1]);
            pah[1] = pkh2(sf[2 * kp][2],     sf[2 * kp][3]);
            pah[2] = pkh2(sf[2 * kp + 1][0], sf[2 * kp + 1][1]);
            pah[3] = pkh2(sf[2 * kp + 1][2], sf[2 * kp + 1][3]);
#pragma unroll
            for (int dp = 0; dp < 4; dp++) {
                uint32_t bvh[4];
                uint32_t vo = (uint32_t)(
                    (kp * 16 + (lane & 15)) * AROWB +
                    (dp * 16 + (lane >> 4) * 8) * 2);
                ldsm4t(bvh, kb + ATILE + vo);
#pragma unroll
                for (int ns = 0; ns < 2; ns++)
                    mma16816h(ov[dp * 2 + ns], pah, &bvh[ns * 2]);
            }
        }
    }

    // epilogue: normalize, fp16 RN, write [b, s, h*64 + d]
    const float inv0 = 1.f / l0;
    const float inv1 = 1.f / l1;
    const int s0 = qt * 64 + wid * 16 + (lane >> 2);
    const size_t row0 = ((size_t)b * S + s0) * DM + h * DH;
    const size_t row1 = row0 + (size_t)8 * DM;
#pragma unroll
    for (int o = 0; o < 8; o++) {
        int d = o * 8 + (lane & 3) * 2;
        *(uint32_t*)(AOh + row0 + d) = pkh2(ov[o][0] * inv0, ov[o][1] * inv0);
        *(uint32_t*)(AOh + row1 + d) = pkh2(ov[o][2] * inv1, ov[o][3] * inv1);
    }
}

// ---------------------------------------------------------------------------
extern "C" void kernel_launch(void* const* d_in, const int* in_sizes, int n_in,
                              void* d_out, int out_size) {
    const float* w[4] = {nullptr, nullptr, nullptr, nullptr};
    const float* x = nullptr;
    int wn = 0;
    for (int i = 0; i < n_in; i++) {
        if (in_sizes[i] == DM * DM && wn < 4) {
            w[wn++] = (const float*)d_in[i];
        } else if (in_sizes[i] == B * S * DM) {
            x = (const float*)d_in[i];
        }
    }

    __half *xh, *whi, *qkvh, *aoh;
    cudaGetSymbolAddress((void**)&xh, g_xh);
    cudaGetSymbolAddress((void**)&whi, g_whi);
    cudaGetSymbolAddress((void**)&qkvh, g_qkvh);
    cudaGetSymbolAddress((void**)&aoh, g_aoh);

    cudaFuncSetAttribute(gemm_f16<0>, cudaFuncAttributeMaxDynamicSharedMemorySize, GEMM_SMEM);
    cudaFuncSetAttribute(gemm_f16<1>, cudaFuncAttributeMaxDynamicSharedMemorySize, GEMM_SMEM);
    cudaFuncSetAttribute(attn_mma, cudaFuncAttributeMaxDynamicSharedMemorySize, ATT_SMEM);

    split_all<<<(SPLIT_TOTAL + 255) / 256, 256>>>(
        (const float4*)x, (const float4*)w[0], (const float4*)w[1],
        (const float4*)w[2], (const float4*)w[3],
        (uint32_t*)xh, (uint32_t*)whi);

    dim3 qkvgrid(3 * DM / 128, M / 128);  // (24, 64)
    gemm_f16<1><<<qkvgrid, 256, GEMM_SMEM>>>(xh, whi, nullptr, qkvh);

    dim3 agrid(S / 64, H, B);  // (32, 16, 4)
    attn_mma<<<agrid, 128, ATT_SMEM>>>(qkvh, aoh);

    dim3 ogrid(DM / 128, M / 128);  // (8, 64)
    gemm_f16<0><<<ogrid, 256, GEMM_SMEM>>>(aoh, whi + (size_t)3 * DM * DM,
                                           (float*)d_out, nullptr);
}